// round 13
// baseline (speedup 1.0000x reference)
#include <cuda_runtime.h>
#include <cuda_bf16.h>
#include <cstdint>

// Problem constants
#define Bc   8
#define Sc   1024
#define Dc   768
#define Hc   12
#define DHc  64
#define Mrows (Bc*Sc)          // 8192
#define QHALF (Sc/2)           // 512

// ---------------------------------------------------------------------------
// Device scratch (allocation-free)
// ---------------------------------------------------------------------------
__device__ float g_Q[(size_t)Bc*Hc*Sc*DHc];   // tf32, pre-scaled 1/8 (q<512 valid)
__device__ float g_K[(size_t)Bc*Hc*Sc*DHc];   // tf32
__device__ float g_V[(size_t)Bc*Hc*Sc*DHc];   // tf32
__device__ float g_ctx[(size_t)Bc*Sc*Dc];     // q<512 rows used
__device__ float g_Wt[4][(size_t)Dc*Dc];      // W^T tf32-rounded: q,k,v,o
__device__ float g_mean[Bc*Dc];               // meanctx [B,D]
__device__ float g_meanrow[Bc*Dc];            // meanctx @ Wo + bo [B,D]

// ---------------------------------------------------------------------------
// Helpers
// ---------------------------------------------------------------------------
__device__ __forceinline__ uint32_t smem_u32(const void* p) {
    uint32_t a;
    asm("{ .reg .u64 t; cvta.to.shared.u64 t, %1; cvt.u32.u64 %0, t; }"
        : "=r"(a) : "l"(p));
    return a;
}
__device__ __forceinline__ float tf32r(float x) {
    float r; asm("cvt.rna.tf32.f32 %0, %1;" : "=f"(r) : "f"(x)); return r;
}
__device__ __forceinline__ uint32_t tf32u(uint32_t w) {
    float f = __uint_as_float(w);
    asm("cvt.rna.tf32.f32 %0, %0;" : "+f"(f));
    return __float_as_uint(f);
}
__device__ __forceinline__ uint32_t lds32(uint32_t a) {
    uint32_t v; asm volatile("ld.shared.b32 %0, [%1];" : "=r"(v) : "r"(a)); return v;
}
__device__ __forceinline__ void sts64(uint32_t a, float x, float y) {
    asm volatile("st.shared.v2.f32 [%0], {%1,%2};" :: "r"(a), "f"(x), "f"(y) : "memory");
}
#define CP_ASYNC16(dst, src) \
    asm volatile("cp.async.cg.shared.global [%0], [%1], 16;" :: "r"(dst), "l"(src) : "memory")
#define CP_COMMIT() asm volatile("cp.async.commit_group;" ::: "memory")
#define CP_WAIT(n)  asm volatile("cp.async.wait_group %0;" :: "n"(n) : "memory")

__device__ __forceinline__ void mma_tf32_16n8k8(float* d, const uint32_t* a, const uint32_t* b) {
    asm volatile(
        "mma.sync.aligned.m16n8k8.row.col.f32.tf32.tf32.f32 "
        "{%0,%1,%2,%3}, {%4,%5,%6,%7}, {%8,%9}, {%0,%1,%2,%3};"
        : "+f"(d[0]), "+f"(d[1]), "+f"(d[2]), "+f"(d[3])
        : "r"(a[0]), "r"(a[1]), "r"(a[2]), "r"(a[3]), "r"(b[0]), "r"(b[1]));
}

// ---------------------------------------------------------------------------
// prep_w3: Wt[z][n*768+k] = tf32(W[k*768+n]) for z in {0,1,2}. grid (24,24,3)
// prep_w1: same for Wo only (side stream).
// ---------------------------------------------------------------------------
__global__ __launch_bounds__(256)
void prep_w3(const float* __restrict__ Wq, const float* __restrict__ Wk,
             const float* __restrict__ Wv)
{
    const float* W = (blockIdx.z == 0) ? Wq : (blockIdx.z == 1) ? Wk : Wv;
    float* Wt = g_Wt[blockIdx.z];
    __shared__ float tile[32][33];
    int tx = threadIdx.x & 31, ty = threadIdx.x >> 5;
    int c0 = blockIdx.x * 32, r0 = blockIdx.y * 32;
    #pragma unroll
    for (int i = 0; i < 4; i++)
        tile[ty + 8*i][tx] = W[(size_t)(r0 + ty + 8*i) * Dc + c0 + tx];
    __syncthreads();
    #pragma unroll
    for (int i = 0; i < 4; i++)
        Wt[(size_t)(c0 + ty + 8*i) * Dc + r0 + tx] = tf32r(tile[tx][ty + 8*i]);
}

__global__ __launch_bounds__(256)
void prep_w1(const float* __restrict__ W)
{
    float* Wt = g_Wt[3];
    __shared__ float tile[32][33];
    int tx = threadIdx.x & 31, ty = threadIdx.x >> 5;
    int c0 = blockIdx.x * 32, r0 = blockIdx.y * 32;
    #pragma unroll
    for (int i = 0; i < 4; i++)
        tile[ty + 8*i][tx] = W[(size_t)(r0 + ty + 8*i) * Dc + c0 + tx];
    __syncthreads();
    #pragma unroll
    for (int i = 0; i < 4; i++)
        Wt[(size_t)(c0 + ty + 8*i) * Dc + r0 + tx] = tf32r(tile[tx][ty + 8*i]);
}

// ---------------------------------------------------------------------------
// mma.sync tf32 GEMM (R11 mainloop, verbatim). MODE 1 takes y_off so the
// out-GEMM can be launched in batch-halves.
// ---------------------------------------------------------------------------
#define BM 128
#define BN 128
#define BK 32
#define KCHUNKS (Dc/BK)           // 24
#define STAGE_BYTES 32768
#define SMEM_DYN (2*STAGE_BYTES)  // 64KB

template<int MODE>
__global__ __launch_bounds__(256, 2)
void gemm_mma(const float* __restrict__ Ain,
              const float* __restrict__ bias0, const float* __restrict__ bias1,
              const float* __restrict__ bias2, float* __restrict__ outp,
              int y_off)
{
    const int z  = (MODE == 0) ? (int)blockIdx.z : 3;
    const int y  = (int)blockIdx.y + y_off;
    const int m0 = (MODE == 0) ? y * BM
                               : (y >> 2) * Sc + (y & 3) * BM;
    if (MODE == 0 && z == 0 && (m0 & (Sc - 1)) >= QHALF) return;

    extern __shared__ char smem[];
    const uint32_t smem_base = smem_u32(smem);
    const int t    = threadIdx.x;
    const int wid  = t >> 5, lane = t & 31;
    const int g    = lane >> 2, tg = lane & 3;
    const int wm   = (wid & 1) * 64;
    const int wn   = (wid >> 1) * 32;

    const int n0 = blockIdx.x * BN;
    const float* __restrict__ A  = (MODE == 0) ? Ain : g_ctx;
    const float* __restrict__ Wt = g_Wt[z];
    const float* __restrict__ bias =
        (MODE == 0) ? (z == 0 ? bias0 : (z == 1 ? bias1 : bias2)) : bias0;

    uint32_t dstoff[4];
    const float* srcA[4];
    const float* srcB[4];
    #pragma unroll
    for (int r = 0; r < 4; r++) {
        int f = t + r * 256;
        int row = f >> 3, c4 = f & 7;
        dstoff[r] = row * 128 + ((c4 * 16) ^ ((row & 7) << 4));
        srcA[r] = &A [(size_t)(m0 + row) * Dc + c4 * 4];
        srcB[r] = &Wt[(size_t)(n0 + row) * Dc + c4 * 4];
    }

    float acc[4][4][4];
    #pragma unroll
    for (int mt = 0; mt < 4; mt++)
        #pragma unroll
        for (int nt = 0; nt < 4; nt++)
            #pragma unroll
            for (int e = 0; e < 4; e++) acc[mt][nt][e] = 0.f;

    {
        uint32_t sA = smem_base, sB = smem_base + 16384;
        #pragma unroll
        for (int r = 0; r < 4; r++) {
            CP_ASYNC16(sA + dstoff[r], srcA[r]);
            CP_ASYNC16(sB + dstoff[r], srcB[r]);
        }
        CP_COMMIT();
    }

    for (int i = 0; i < KCHUNKS; i++) {
        const int s = i & 1;
        if (i + 1 < KCHUNKS) {
            uint32_t sA = smem_base + (s ^ 1) * STAGE_BYTES, sB = sA + 16384;
            const int k0 = (i + 1) * BK;
            #pragma unroll
            for (int r = 0; r < 4; r++) {
                CP_ASYNC16(sA + dstoff[r], srcA[r] + k0);
                CP_ASYNC16(sB + dstoff[r], srcB[r] + k0);
            }
            CP_COMMIT();
            CP_WAIT(1);
        } else {
            CP_WAIT(0);
        }
        __syncthreads();

        const uint32_t sA = smem_base + s * STAGE_BYTES;
        const uint32_t sB = sA + 16384;
        const uint32_t gx = (uint32_t)(g << 4);

        #pragma unroll
        for (int kk = 0; kk < 4; kk++) {
            const uint32_t c0 = (uint32_t)((kk * 8 + tg) * 4) ^ gx;
            const uint32_t c1 = (uint32_t)((kk * 8 + tg + 4) * 4) ^ gx;
            uint32_t a[4][4];
            #pragma unroll
            for (int mt = 0; mt < 4; mt++) {
                uint32_t base = sA + (wm + mt * 16 + g) * 128;
                a[mt][0] = lds32(base + c0);
                a[mt][1] = lds32(base + 1024 + c0);
                a[mt][2] = lds32(base + c1);
                a[mt][3] = lds32(base + 1024 + c1);
                if (MODE == 0) {
                    a[mt][0] = tf32u(a[mt][0]);
                    a[mt][1] = tf32u(a[mt][1]);
                    a[mt][2] = tf32u(a[mt][2]);
                    a[mt][3] = tf32u(a[mt][3]);
                }
            }
            uint32_t b[4][2];
            #pragma unroll
            for (int nt = 0; nt < 4; nt++) {
                uint32_t base = sB + (wn + nt * 8 + g) * 128;
                b[nt][0] = lds32(base + c0);
                b[nt][1] = lds32(base + c1);
            }
            #pragma unroll
            for (int mt = 0; mt < 4; mt++)
                #pragma unroll
                for (int nt = 0; nt < 4; nt++)
                    mma_tf32_16n8k8(acc[mt][nt], a[mt], b[nt]);
        }
        __syncthreads();
    }

    #pragma unroll
    for (int nt = 0; nt < 4; nt++) {
        const int col = n0 + wn + nt * 8 + tg * 2;
        const float b0 = bias[col], b1 = bias[col + 1];
        #pragma unroll
        for (int mt = 0; mt < 4; mt++) {
            const int row = m0 + wm + mt * 16 + g;
            float x0 = acc[mt][nt][0] + b0, y0 = acc[mt][nt][1] + b1;
            float x1 = acc[mt][nt][2] + b0, y1 = acc[mt][nt][3] + b1;
            if (MODE == 0) {
                const int h = col >> 6, dh = col & 63;
                int bA = row >> 10, sL = row & 1023;
                size_t i0 = (((size_t)bA * Hc + h) * Sc + sL) * DHc + dh;
                int row1 = row + 8;
                int bB = row1 >> 10, sM = row1 & 1023;
                size_t i1 = (((size_t)bB * Hc + h) * Sc + sM) * DHc + dh;
                float* out = (z == 0) ? g_Q : (z == 1) ? g_K : g_V;
                if (z == 0) { x0 *= 0.125f; y0 *= 0.125f; x1 *= 0.125f; y1 *= 0.125f; }
                *(float2*)&out[i0] = make_float2(tf32r(x0), tf32r(y0));
                *(float2*)&out[i1] = make_float2(tf32r(x1), tf32r(y1));
            } else {
                *(float2*)&outp[(size_t)row * Dc + col] = make_float2(x0, y0);
                *(float2*)&outp[(size_t)(row + 8) * Dc + col] = make_float2(x1, y1);
            }
        }
    }
}

// ---------------------------------------------------------------------------
// meanv_mean: per-(b,h) mean of V -> g_mean. grid 96 x 256.
// ---------------------------------------------------------------------------
__global__ __launch_bounds__(256)
void meanv_mean()
{
    const int bh = blockIdx.x;
    const float* Vbh = g_V + (size_t)bh * Sc * DHc;
    __shared__ float part[4][64];
    const int t  = threadIdx.x;
    const int dh = t & 63, c = t >> 6;
    float sum = 0.f;
    for (int s = c * 256; s < (c + 1) * 256; s++) sum += Vbh[s * DHc + dh];
    part[c][dh] = sum;
    __syncthreads();
    if (t < 64)
        g_mean[bh * 64 + t] =
            tf32r((part[0][t] + part[1][t] + part[2][t] + part[3][t]) * (1.0f / Sc));
}

// meanrow_gemm: g_meanrow[b][n] = g_mean[b].Wt3[n] + bo[n]. grid 768 x 256.
__global__ __launch_bounds__(256)
void meanrow_gemm(const float* __restrict__ bo)
{
    const int idx  = blockIdx.x * 8 + (threadIdx.x >> 5);
    const int lane = threadIdx.x & 31;
    const int b = idx / Dc, n = idx % Dc;
    const float* m = g_mean + b * Dc;
    const float* w = g_Wt[3] + (size_t)n * Dc;
    float s = 0.f;
    #pragma unroll 4
    for (int d = lane; d < Dc; d += 32) s += m[d] * w[d];
    #pragma unroll
    for (int o = 16; o; o >>= 1) s += __shfl_xor_sync(0xffffffffu, s, o);
    if (lane == 0) g_meanrow[idx] = s + bo[n];
}

// bcast_out: d_out rows q in [512,1024) = g_meanrow[b]. grid 3072 x 256.
__global__ __launch_bounds__(256)
void bcast_out(float* __restrict__ out)
{
    const int i = blockIdx.x * 256 + threadIdx.x;
    const int b = i / 98304;
    const int rem = i - b * 98304;
    const int q = rem / 192;
    const int d4 = rem - q * 192;
    float4 v = ((const float4*)(g_meanrow + b * Dc))[d4];
    ((float4*)(out + ((size_t)b * Sc + QHALF + q) * Dc))[d4] = v;
}

// ---------------------------------------------------------------------------
// Flash mma attention, q<512 (R9/R11 version; only bh_off added).
// grid (4, 48) x 2 launches. 8 warps = 4M x 2N. Smem 112KB -> 2 CTAs/SM.
// ---------------------------------------------------------------------------
#define NCHUNKS 16
#define SK0 32768
#define SK1 49152
#define SV  65536
#define SP2 81920
#define SL2 32768
#define ATT_SMEM 114688

__global__ __launch_bounds__(256, 2)
void attn_mma(int bh_off)
{
    extern __shared__ char sm[];
    const uint32_t sb = smem_u32(sm);
    const int t = threadIdx.x;
    const int wid = t >> 5, lane = t & 31;
    const int g = lane >> 2, tg = lane & 3;
    const int wm = (wid >> 1) * 32;
    const int wn = (wid & 1) * 32;
    const int bh = blockIdx.y + bh_off;
    const int q0 = blockIdx.x * 128;
    const size_t kvbase = (size_t)bh * Sc * DHc;

    const float* Qp = g_Q + kvbase + (size_t)q0 * DHc;
    const float* Kp = g_K + kvbase;
    const float* Vp = g_V + kvbase;

    #pragma unroll
    for (int r = 0; r < 8; r++) {
        int f = t + r * 256, row = f >> 4, c = f & 15;
        CP_ASYNC16(sb + row * 256 + ((c * 16) ^ ((row & 7) << 4)),
                   Qp + (size_t)row * 64 + c * 4);
    }
    #pragma unroll
    for (int r = 0; r < 4; r++) {
        int f = t + r * 256, row = f >> 4, c = f & 15;
        uint32_t dk = row * 256 + ((c * 16) ^ ((row & 7) << 4));
        uint32_t dv = row * 256 + ((c * 16) ^ ((row & 3) << 5));
        CP_ASYNC16(sb + SK0 + dk, Kp + (size_t)row * 64 + c * 4);
        CP_ASYNC16(sb + SV  + dv, Vp + (size_t)row * 64 + c * 4);
        CP_ASYNC16(sb + SK1 + dk, Kp + (size_t)(64 + row) * 64 + c * 4);
    }
    CP_COMMIT();
    CP_WAIT(0);
    __syncthreads();

    float oacc[2][4][4];
    #pragma unroll
    for (int mt = 0; mt < 2; mt++)
        #pragma unroll
        for (int nt = 0; nt < 4; nt++)
            #pragma unroll
            for (int e = 0; e < 4; e++) oacc[mt][nt][e] = 0.f;
    float lacc[4] = {0.f, 0.f, 0.f, 0.f};

    for (int j = 0; j < NCHUNKS; j++) {
        const uint32_t kst = sb + ((j & 1) ? SK1 : SK0);

        float sacc[2][4][4];
        #pragma unroll
        for (int mt = 0; mt < 2; mt++)
            #pragma unroll
            for (int nt = 0; nt < 4; nt++)
                #pragma unroll
                for (int e = 0; e < 4; e++) sacc[mt][nt][e] = 0.f;

        #pragma unroll
        for (int kk = 0; kk < 8; kk++) {
            const uint32_t c0 = (kk * 8 + tg) * 4;
            const uint32_t c1 = c0 + 16;
            const uint32_t xr = (uint32_t)(g << 4);
            uint32_t a[2][4];
            #pragma unroll
            for (int mt = 0; mt < 2; mt++) {
                const uint32_t b0a = sb + (wm + mt * 16 + g) * 256;
                a[mt][0] = lds32(b0a + (c0 ^ xr));
                a[mt][1] = lds32(b0a + 2048 + (c0 ^ xr));
                a[mt][2] = lds32(b0a + (c1 ^ xr));
                a[mt][3] = lds32(b0a + 2048 + (c1 ^ xr));
            }
            #pragma unroll
            for (int nt = 0; nt < 4; nt++) {
                const uint32_t bk = kst + (wn + nt * 8 + g) * 256;
                uint32_t bf[2];
                bf[0] = lds32(bk + (c0 ^ xr));
                bf[1] = lds32(bk + (c1 ^ xr));
                mma_tf32_16n8k8(sacc[0][nt], a[0], bf);
                mma_tf32_16n8k8(sacc[1][nt], a[1], bf);
            }
        }

        #pragma unroll
        for (int mt = 0; mt < 2; mt++) {
            #pragma unroll
            for (int nt = 0; nt < 4; nt++) {
                float p0 = tf32r(__expf(sacc[mt][nt][0]));
                float p1 = tf32r(__expf(sacc[mt][nt][1]));
                float p2 = tf32r(__expf(sacc[mt][nt][2]));
                float p3 = tf32r(__expf(sacc[mt][nt][3]));
                lacc[2*mt]     += p0 + p1;
                lacc[2*mt + 1] += p2 + p3;
                const uint32_t col = (uint32_t)(wn + nt * 8 + 2 * tg);
                const uint32_t a0 = sb + SP2 + (wm + mt * 16 + g) * 256
                                    + ((col * 4) ^ ((uint32_t)g << 4));
                sts64(a0, p0, p1);
                sts64(a0 + 2048, p2, p3);
            }
        }
        __syncthreads();
        CP_WAIT(0);

        #pragma unroll
        for (int kk = 0; kk < 8; kk++) {
            const uint32_t c0 = (kk * 8 + tg) * 4;
            const uint32_t c1 = c0 + 16;
            const uint32_t xr = (uint32_t)(g << 4);
            uint32_t ap[2][4];
            #pragma unroll
            for (int mt = 0; mt < 2; mt++) {
                const uint32_t pb = sb + SP2 + (wm + mt * 16 + g) * 256;
                ap[mt][0] = lds32(pb + (c0 ^ xr));
                ap[mt][1] = lds32(pb + 2048 + (c0 ^ xr));
                ap[mt][2] = lds32(pb + (c1 ^ xr));
                ap[mt][3] = lds32(pb + 2048 + (c1 ^ xr));
            }
            const uint32_t r0 = (kk * 8 + tg) * 256;
            const uint32_t r1 = r0 + 4 * 256;
            const uint32_t xv = (uint32_t)(tg << 5);
            #pragma unroll
            for (int nt = 0; nt < 4; nt++) {
                const uint32_t cb = (uint32_t)((wn + nt * 8 + g) * 4);
                uint32_t bv[2];
                bv[0] = lds32(sb + SV + r0 + (cb ^ xv));
                bv[1] = lds32(sb + SV + r1 + (cb ^ xv));
                mma_tf32_16n8k8(oacc[0][nt], ap[0], bv);
                mma_tf32_16n8k8(oacc[1][nt], ap[1], bv);
            }
        }
        __syncthreads();

        if (j + 1 < NCHUNKS) {
            const int kv = (j + 1) * 64;
            #pragma unroll
            for (int r = 0; r < 4; r++) {
                int f = t + r * 256, row = f >> 4, c = f & 15;
                uint32_t dv = row * 256 + ((c * 16) ^ ((row & 3) << 5));
                CP_ASYNC16(sb + SV + dv, Vp + (size_t)(kv + row) * 64 + c * 4);
            }
            if (j + 2 < NCHUNKS) {
                const int kk2 = (j + 2) * 64;
                #pragma unroll
                for (int r = 0; r < 4; r++) {
                    int f = t + r * 256, row = f >> 4, c = f & 15;
                    uint32_t dk = row * 256 + ((c * 16) ^ ((row & 7) << 4));
                    CP_ASYNC16(kst + dk, Kp + (size_t)(kk2 + row) * 64 + c * 4);
                }
            }
        }
        CP_COMMIT();
    }

    #pragma unroll
    for (int j = 0; j < 4; j++) {
        lacc[j] += __shfl_xor_sync(0xffffffff, lacc[j], 1);
        lacc[j] += __shfl_xor_sync(0xffffffff, lacc[j], 2);
    }
    if (tg == 0) {
        float* lp = (float*)(sm + SL2);
        #pragma unroll
        for (int j = 0; j < 4; j++) {
            int row = wm + (j >> 1) * 16 + (j & 1) * 8 + g;
            lp[(wid & 1) * 128 + row] = lacc[j];
        }
    }
    __syncthreads();

    const int b = bh / Hc, h = bh % Hc;
    float* ctxb = g_ctx + ((size_t)b * Sc + q0) * Dc + h * DHc;
    const float* lp = (const float*)(sm + SL2);
    #pragma unroll
    for (int mt = 0; mt < 2; mt++) {
        #pragma unroll
        for (int e = 0; e < 2; e++) {
            const int row = wm + mt * 16 + e * 8 + g;
            const float inv = 1.0f / (lp[row] + lp[128 + row]);
            #pragma unroll
            for (int nt = 0; nt < 4; nt++) {
                const int col = wn + nt * 8 + 2 * tg;
                float v0 = tf32r(oacc[mt][nt][2*e]     * inv);
                float v1 = tf32r(oacc[mt][nt][2*e + 1] * inv);
                *(float2*)&ctxb[(size_t)row * Dc + col] = make_float2(v0, v1);
            }
        }
    }
}

// ---------------------------------------------------------------------------
extern "C" void kernel_launch(void* const* d_in, const int* in_sizes, int n_in,
                              void* d_out, int out_size)
{
    const float* X  = (const float*)d_in[0];
    const float* Wq = (const float*)d_in[1];
    const float* bq = (const float*)d_in[2];
    const float* Wk = (const float*)d_in[3];
    const float* bk = (const float*)d_in[4];
    const float* Wv = (const float*)d_in[5];
    const float* bv = (const float*)d_in[6];
    const float* Wo = (const float*)d_in[7];
    const float* bo = (const float*)d_in[8];
    float* out = (float*)d_out;

    cudaFuncSetAttribute(gemm_mma<0>, cudaFuncAttributeMaxDynamicSharedMemorySize, SMEM_DYN);
    cudaFuncSetAttribute(gemm_mma<1>, cudaFuncAttributeMaxDynamicSharedMemorySize, SMEM_DYN);
    cudaFuncSetAttribute(attn_mma, cudaFuncAttributeMaxDynamicSharedMemorySize, ATT_SMEM);

    // Streams: s2 = Wo transpose + mean/broadcast branch; s3 = out-GEMM halves
    // overlapped with the 2nd attention half. Host objects only; allocation-free.
    cudaStream_t s2, s3;
    cudaStreamCreateWithFlags(&s2, cudaStreamNonBlocking);
    cudaStreamCreateWithFlags(&s3, cudaStreamNonBlocking);
    cudaEvent_t eFork0, eQKV, eWo, eA1, eA2, eJoin2, eJoin3;
    cudaEventCreateWithFlags(&eFork0, cudaEventDisableTiming);
    cudaEventCreateWithFlags(&eQKV,   cudaEventDisableTiming);
    cudaEventCreateWithFlags(&eWo,    cudaEventDisableTiming);
    cudaEventCreateWithFlags(&eA1,    cudaEventDisableTiming);
    cudaEventCreateWithFlags(&eA2,    cudaEventDisableTiming);
    cudaEventCreateWithFlags(&eJoin2, cudaEventDisableTiming);
    cudaEventCreateWithFlags(&eJoin3, cudaEventDisableTiming);

    // Fork s2 at graph start; s2 transposes Wo while main does q/k/v + QKV GEMM.
    cudaEventRecord(eFork0, 0);
    cudaStreamWaitEvent(s2, eFork0, 0);
    prep_w1<<<dim3(24, 24), 256, 0, s2>>>(Wo);
    cudaEventRecord(eWo, s2);

    prep_w3<<<dim3(24, 24, 3), 256>>>(Wq, Wk, Wv);

    gemm_mma<0><<<dim3(Dc/BN, Mrows/BM, 3), 256, SMEM_DYN>>>(X, bq, bk, bv, nullptr, 0);

    // Branch B on s2 (needs V from gemm0 and Wt[3] from prep_w1).
    cudaEventRecord(eQKV, 0);
    cudaStreamWaitEvent(s2, eQKV, 0);
    meanv_mean<<<96, 256, 0, s2>>>();
    meanrow_gemm<<<768, 256, 0, s2>>>(bo);
    bcast_out<<<3072, 256, 0, s2>>>(out);
    cudaEventRecord(eJoin2, s2);

    // Attention in two batch-halves; out-GEMM halves chase them on s3.
    attn_mma<<<dim3(4, 48), 256, ATT_SMEM>>>(0);     // bh 0..47 (batches 0-3)
    cudaEventRecord(eA1, 0);
    attn_mma<<<dim3(4, 48), 256, ATT_SMEM>>>(48);    // bh 48..95 (batches 4-7)
    cudaEventRecord(eA2, 0);

    cudaStreamWaitEvent(s3, eWo, 0);
    cudaStreamWaitEvent(s3, eA1, 0);
    gemm_mma<1><<<dim3(Dc/BN, 16), 256, SMEM_DYN, s3>>>(nullptr, bo, bo, bo, out, 0);
    cudaStreamWaitEvent(s3, eA2, 0);
    gemm_mma<1><<<dim3(Dc/BN, 16), 256, SMEM_DYN, s3>>>(nullptr, bo, bo, bo, out, 16);
    cudaEventRecord(eJoin3, s3);

    cudaStreamWaitEvent(0, eJoin2, 0);
    cudaStreamWaitEvent(0, eJoin3, 0);

    cudaEventDestroy(eFork0);
    cudaEventDestroy(eQKV);
    cudaEventDestroy(eWo);
    cudaEventDestroy(eA1);
    cudaEventDestroy(eA2);
    cudaEventDestroy(eJoin2);
    cudaEventDestroy(eJoin3);
    cudaStreamDestroy(s2);
    cudaStreamDestroy(s3);
}

// round 14
// speedup vs baseline: 1.0767x; 1.0767x over previous
#include <cuda_runtime.h>
#include <cuda_bf16.h>
#include <cstdint>

// Problem constants
#define Bc   8
#define Sc   1024
#define Dc   768
#define Hc   12
#define DHc  64
#define Mrows (Bc*Sc)          // 8192
#define QHALF (Sc/2)           // 512

// ---------------------------------------------------------------------------
// Device scratch (allocation-free)
// ---------------------------------------------------------------------------
__device__ float g_Q[(size_t)Bc*Hc*Sc*DHc];   // tf32, pre-scaled 1/8 (q<512 valid)
__device__ float g_K[(size_t)Bc*Hc*Sc*DHc];   // tf32
__device__ float g_V[(size_t)Bc*Hc*Sc*DHc];   // tf32
__device__ float g_ctx[(size_t)Bc*Sc*Dc];     // q<512 rows used
__device__ float g_Wt[4][(size_t)Dc*Dc];      // W^T tf32-rounded: q,k,v,o
__device__ float g_Xr[(size_t)Mrows*Dc];      // X tf32-rounded
__device__ float g_mean[Bc*Dc];               // meanctx [B,D]
__device__ float g_meanrow[Bc*Dc];            // meanctx @ Wo + bo [B,D]

// ---------------------------------------------------------------------------
// Helpers
// ---------------------------------------------------------------------------
__device__ __forceinline__ uint32_t smem_u32(const void* p) {
    uint32_t a;
    asm("{ .reg .u64 t; cvta.to.shared.u64 t, %1; cvt.u32.u64 %0, t; }"
        : "=r"(a) : "l"(p));
    return a;
}
__device__ __forceinline__ float tf32r(float x) {
    float r; asm("cvt.rna.tf32.f32 %0, %1;" : "=f"(r) : "f"(x)); return r;
}
__device__ __forceinline__ uint32_t lds32(uint32_t a) {
    uint32_t v; asm volatile("ld.shared.b32 %0, [%1];" : "=r"(v) : "r"(a)); return v;
}
__device__ __forceinline__ void sts64(uint32_t a, float x, float y) {
    asm volatile("st.shared.v2.f32 [%0], {%1,%2};" :: "r"(a), "f"(x), "f"(y) : "memory");
}
#define CP_ASYNC16(dst, src) \
    asm volatile("cp.async.cg.shared.global [%0], [%1], 16;" :: "r"(dst), "l"(src) : "memory")
#define CP_COMMIT() asm volatile("cp.async.commit_group;" ::: "memory")
#define CP_WAIT(n)  asm volatile("cp.async.wait_group %0;" :: "n"(n) : "memory")

__device__ __forceinline__ void mma_tf32_16n8k8(float* d, const uint32_t* a, const uint32_t* b) {
    asm volatile(
        "mma.sync.aligned.m16n8k8.row.col.f32.tf32.tf32.f32 "
        "{%0,%1,%2,%3}, {%4,%5,%6,%7}, {%8,%9}, {%0,%1,%2,%3};"
        : "+f"(d[0]), "+f"(d[1]), "+f"(d[2]), "+f"(d[3])
        : "r"(a[0]), "r"(a[1]), "r"(a[2]), "r"(a[3]), "r"(b[0]), "r"(b[1]));
}

// ---------------------------------------------------------------------------
// prep_w3: Wt[z][n*768+k] = tf32(W[k*768+n]) for z in {0,1,2}. grid (24,24,3)
// prep_w1: same for Wo only (side stream).
// prep_x : g_Xr = tf32(X) (side stream, hides behind prep_w3).
// ---------------------------------------------------------------------------
__global__ __launch_bounds__(256)
void prep_w3(const float* __restrict__ Wq, const float* __restrict__ Wk,
             const float* __restrict__ Wv)
{
    const float* W = (blockIdx.z == 0) ? Wq : (blockIdx.z == 1) ? Wk : Wv;
    float* Wt = g_Wt[blockIdx.z];
    __shared__ float tile[32][33];
    int tx = threadIdx.x & 31, ty = threadIdx.x >> 5;
    int c0 = blockIdx.x * 32, r0 = blockIdx.y * 32;
    #pragma unroll
    for (int i = 0; i < 4; i++)
        tile[ty + 8*i][tx] = W[(size_t)(r0 + ty + 8*i) * Dc + c0 + tx];
    __syncthreads();
    #pragma unroll
    for (int i = 0; i < 4; i++)
        Wt[(size_t)(c0 + ty + 8*i) * Dc + r0 + tx] = tf32r(tile[tx][ty + 8*i]);
}

__global__ __launch_bounds__(256)
void prep_w1(const float* __restrict__ W)
{
    float* Wt = g_Wt[3];
    __shared__ float tile[32][33];
    int tx = threadIdx.x & 31, ty = threadIdx.x >> 5;
    int c0 = blockIdx.x * 32, r0 = blockIdx.y * 32;
    #pragma unroll
    for (int i = 0; i < 4; i++)
        tile[ty + 8*i][tx] = W[(size_t)(r0 + ty + 8*i) * Dc + c0 + tx];
    __syncthreads();
    #pragma unroll
    for (int i = 0; i < 4; i++)
        Wt[(size_t)(c0 + ty + 8*i) * Dc + r0 + tx] = tf32r(tile[tx][ty + 8*i]);
}

__global__ __launch_bounds__(256)
void prep_x(const float* __restrict__ X)
{
    const int N4 = Mrows * Dc / 4;
    for (int i = blockIdx.x * blockDim.x + threadIdx.x; i < N4; i += gridDim.x * blockDim.x) {
        float4 v = ((const float4*)X)[i];
        v.x = tf32r(v.x); v.y = tf32r(v.y); v.z = tf32r(v.z); v.w = tf32r(v.w);
        ((float4*)g_Xr)[i] = v;
    }
}

// ---------------------------------------------------------------------------
// mma.sync tf32 GEMM (R11 mainloop; A always pre-rounded -> no mainloop cvts).
// MODE 0: A = g_Xr, z->Q/K/V; z==0 skips tiles with in-batch row >= 512.
// MODE 1: A = g_ctx, Wt=g_Wt[3], out = d_out rows q<512.
// ---------------------------------------------------------------------------
#define BM 128
#define BN 128
#define BK 32
#define KCHUNKS (Dc/BK)           // 24
#define STAGE_BYTES 32768
#define SMEM_DYN (2*STAGE_BYTES)  // 64KB

template<int MODE>
__global__ __launch_bounds__(256, 2)
void gemm_mma(const float* __restrict__ bias0, const float* __restrict__ bias1,
              const float* __restrict__ bias2, float* __restrict__ outp)
{
    const int z  = (MODE == 0) ? (int)blockIdx.z : 3;
    const int m0 = (MODE == 0) ? (int)blockIdx.y * BM
                               : ((int)blockIdx.y >> 2) * Sc + ((int)blockIdx.y & 3) * BM;
    if (MODE == 0 && z == 0 && (m0 & (Sc - 1)) >= QHALF) return;

    extern __shared__ char smem[];
    const uint32_t smem_base = smem_u32(smem);
    const int t    = threadIdx.x;
    const int wid  = t >> 5, lane = t & 31;
    const int g    = lane >> 2, tg = lane & 3;
    const int wm   = (wid & 1) * 64;
    const int wn   = (wid >> 1) * 32;

    const int n0 = blockIdx.x * BN;
    const float* __restrict__ A  = (MODE == 0) ? g_Xr : g_ctx;
    const float* __restrict__ Wt = g_Wt[z];
    const float* __restrict__ bias =
        (MODE == 0) ? (z == 0 ? bias0 : (z == 1 ? bias1 : bias2)) : bias0;

    uint32_t dstoff[4];
    const float* srcA[4];
    const float* srcB[4];
    #pragma unroll
    for (int r = 0; r < 4; r++) {
        int f = t + r * 256;
        int row = f >> 3, c4 = f & 7;
        dstoff[r] = row * 128 + ((c4 * 16) ^ ((row & 7) << 4));
        srcA[r] = &A [(size_t)(m0 + row) * Dc + c4 * 4];
        srcB[r] = &Wt[(size_t)(n0 + row) * Dc + c4 * 4];
    }

    float acc[4][4][4];
    #pragma unroll
    for (int mt = 0; mt < 4; mt++)
        #pragma unroll
        for (int nt = 0; nt < 4; nt++)
            #pragma unroll
            for (int e = 0; e < 4; e++) acc[mt][nt][e] = 0.f;

    {
        uint32_t sA = smem_base, sB = smem_base + 16384;
        #pragma unroll
        for (int r = 0; r < 4; r++) {
            CP_ASYNC16(sA + dstoff[r], srcA[r]);
            CP_ASYNC16(sB + dstoff[r], srcB[r]);
        }
        CP_COMMIT();
    }

    for (int i = 0; i < KCHUNKS; i++) {
        const int s = i & 1;
        if (i + 1 < KCHUNKS) {
            uint32_t sA = smem_base + (s ^ 1) * STAGE_BYTES, sB = sA + 16384;
            const int k0 = (i + 1) * BK;
            #pragma unroll
            for (int r = 0; r < 4; r++) {
                CP_ASYNC16(sA + dstoff[r], srcA[r] + k0);
                CP_ASYNC16(sB + dstoff[r], srcB[r] + k0);
            }
            CP_COMMIT();
            CP_WAIT(1);
        } else {
            CP_WAIT(0);
        }
        __syncthreads();

        const uint32_t sA = smem_base + s * STAGE_BYTES;
        const uint32_t sB = sA + 16384;
        const uint32_t gx = (uint32_t)(g << 4);

        #pragma unroll
        for (int kk = 0; kk < 4; kk++) {
            const uint32_t c0 = (uint32_t)((kk * 8 + tg) * 4) ^ gx;
            const uint32_t c1 = (uint32_t)((kk * 8 + tg + 4) * 4) ^ gx;
            uint32_t a[4][4];
            #pragma unroll
            for (int mt = 0; mt < 4; mt++) {
                uint32_t base = sA + (wm + mt * 16 + g) * 128;
                a[mt][0] = lds32(base + c0);
                a[mt][1] = lds32(base + 1024 + c0);
                a[mt][2] = lds32(base + c1);
                a[mt][3] = lds32(base + 1024 + c1);
            }
            uint32_t b[4][2];
            #pragma unroll
            for (int nt = 0; nt < 4; nt++) {
                uint32_t base = sB + (wn + nt * 8 + g) * 128;
                b[nt][0] = lds32(base + c0);
                b[nt][1] = lds32(base + c1);
            }
            #pragma unroll
            for (int mt = 0; mt < 4; mt++)
                #pragma unroll
                for (int nt = 0; nt < 4; nt++)
                    mma_tf32_16n8k8(acc[mt][nt], a[mt], b[nt]);
        }
        __syncthreads();
    }

    #pragma unroll
    for (int nt = 0; nt < 4; nt++) {
        const int col = n0 + wn + nt * 8 + tg * 2;
        const float b0 = bias[col], b1 = bias[col + 1];
        #pragma unroll
        for (int mt = 0; mt < 4; mt++) {
            const int row = m0 + wm + mt * 16 + g;
            float x0 = acc[mt][nt][0] + b0, y0 = acc[mt][nt][1] + b1;
            float x1 = acc[mt][nt][2] + b0, y1 = acc[mt][nt][3] + b1;
            if (MODE == 0) {
                const int h = col >> 6, dh = col & 63;
                int bA = row >> 10, sL = row & 1023;
                size_t i0 = (((size_t)bA * Hc + h) * Sc + sL) * DHc + dh;
                int row1 = row + 8;
                int bB = row1 >> 10, sM = row1 & 1023;
                size_t i1 = (((size_t)bB * Hc + h) * Sc + sM) * DHc + dh;
                float* out = (z == 0) ? g_Q : (z == 1) ? g_K : g_V;
                if (z == 0) { x0 *= 0.125f; y0 *= 0.125f; x1 *= 0.125f; y1 *= 0.125f; }
                *(float2*)&out[i0] = make_float2(tf32r(x0), tf32r(y0));
                *(float2*)&out[i1] = make_float2(tf32r(x1), tf32r(y1));
            } else {
                *(float2*)&outp[(size_t)row * Dc + col] = make_float2(x0, y0);
                *(float2*)&outp[(size_t)(row + 8) * Dc + col] = make_float2(x1, y1);
            }
        }
    }
}

// ---------------------------------------------------------------------------
// meanv_mean: per-(b,h) mean of V -> g_mean. grid 96 x 256.
// ---------------------------------------------------------------------------
__global__ __launch_bounds__(256)
void meanv_mean()
{
    const int bh = blockIdx.x;
    const float* Vbh = g_V + (size_t)bh * Sc * DHc;
    __shared__ float part[4][64];
    const int t  = threadIdx.x;
    const int dh = t & 63, c = t >> 6;
    float sum = 0.f;
    for (int s = c * 256; s < (c + 1) * 256; s++) sum += Vbh[s * DHc + dh];
    part[c][dh] = sum;
    __syncthreads();
    if (t < 64)
        g_mean[bh * 64 + t] =
            tf32r((part[0][t] + part[1][t] + part[2][t] + part[3][t]) * (1.0f / Sc));
}

// meanrow_gemm: g_meanrow[b][n] = g_mean[b].Wt3[n] + bo[n]. grid 768 x 256.
__global__ __launch_bounds__(256)
void meanrow_gemm(const float* __restrict__ bo)
{
    const int idx  = blockIdx.x * 8 + (threadIdx.x >> 5);
    const int lane = threadIdx.x & 31;
    const int b = idx / Dc, n = idx % Dc;
    const float* m = g_mean + b * Dc;
    const float* w = g_Wt[3] + (size_t)n * Dc;
    float s = 0.f;
    #pragma unroll 4
    for (int d = lane; d < Dc; d += 32) s += m[d] * w[d];
    #pragma unroll
    for (int o = 16; o; o >>= 1) s += __shfl_xor_sync(0xffffffffu, s, o);
    if (lane == 0) g_meanrow[idx] = s + bo[n];
}

// bcast_out: d_out rows q in [512,1024) = g_meanrow[b]. grid 3072 x 256.
__global__ __launch_bounds__(256)
void bcast_out(float* __restrict__ out)
{
    const int i = blockIdx.x * 256 + threadIdx.x;
    const int b = i / 98304;
    const int rem = i - b * 98304;
    const int q = rem / 192;
    const int d4 = rem - q * 192;
    float4 v = ((const float4*)(g_meanrow + b * Dc))[d4];
    ((float4*)(out + ((size_t)b * Sc + QHALF + q) * Dc))[d4] = v;
}

// ---------------------------------------------------------------------------
// Flash mma attention, q<512 (R9/R11 version, verbatim). grid (4, 96), 256 thr.
// 8 warps = 4M x 2N. Smem 112KB -> 2 CTAs/SM.
// ---------------------------------------------------------------------------
#define NCHUNKS 16
#define SK0 32768
#define SK1 49152
#define SV  65536
#define SP2 81920
#define SL2 32768
#define ATT_SMEM 114688

__global__ __launch_bounds__(256, 2)
void attn_mma()
{
    extern __shared__ char sm[];
    const uint32_t sb = smem_u32(sm);
    const int t = threadIdx.x;
    const int wid = t >> 5, lane = t & 31;
    const int g = lane >> 2, tg = lane & 3;
    const int wm = (wid >> 1) * 32;
    const int wn = (wid & 1) * 32;
    const int bh = blockIdx.y;
    const int q0 = blockIdx.x * 128;
    const size_t kvbase = (size_t)bh * Sc * DHc;

    const float* Qp = g_Q + kvbase + (size_t)q0 * DHc;
    const float* Kp = g_K + kvbase;
    const float* Vp = g_V + kvbase;

    #pragma unroll
    for (int r = 0; r < 8; r++) {
        int f = t + r * 256, row = f >> 4, c = f & 15;
        CP_ASYNC16(sb + row * 256 + ((c * 16) ^ ((row & 7) << 4)),
                   Qp + (size_t)row * 64 + c * 4);
    }
    #pragma unroll
    for (int r = 0; r < 4; r++) {
        int f = t + r * 256, row = f >> 4, c = f & 15;
        uint32_t dk = row * 256 + ((c * 16) ^ ((row & 7) << 4));
        uint32_t dv = row * 256 + ((c * 16) ^ ((row & 3) << 5));
        CP_ASYNC16(sb + SK0 + dk, Kp + (size_t)row * 64 + c * 4);
        CP_ASYNC16(sb + SV  + dv, Vp + (size_t)row * 64 + c * 4);
        CP_ASYNC16(sb + SK1 + dk, Kp + (size_t)(64 + row) * 64 + c * 4);
    }
    CP_COMMIT();
    CP_WAIT(0);
    __syncthreads();

    float oacc[2][4][4];
    #pragma unroll
    for (int mt = 0; mt < 2; mt++)
        #pragma unroll
        for (int nt = 0; nt < 4; nt++)
            #pragma unroll
            for (int e = 0; e < 4; e++) oacc[mt][nt][e] = 0.f;
    float lacc[4] = {0.f, 0.f, 0.f, 0.f};

    for (int j = 0; j < NCHUNKS; j++) {
        const uint32_t kst = sb + ((j & 1) ? SK1 : SK0);

        float sacc[2][4][4];
        #pragma unroll
        for (int mt = 0; mt < 2; mt++)
            #pragma unroll
            for (int nt = 0; nt < 4; nt++)
                #pragma unroll
                for (int e = 0; e < 4; e++) sacc[mt][nt][e] = 0.f;

        #pragma unroll
        for (int kk = 0; kk < 8; kk++) {
            const uint32_t c0 = (kk * 8 + tg) * 4;
            const uint32_t c1 = c0 + 16;
            const uint32_t xr = (uint32_t)(g << 4);
            uint32_t a[2][4];
            #pragma unroll
            for (int mt = 0; mt < 2; mt++) {
                const uint32_t b0a = sb + (wm + mt * 16 + g) * 256;
                a[mt][0] = lds32(b0a + (c0 ^ xr));
                a[mt][1] = lds32(b0a + 2048 + (c0 ^ xr));
                a[mt][2] = lds32(b0a + (c1 ^ xr));
                a[mt][3] = lds32(b0a + 2048 + (c1 ^ xr));
            }
            #pragma unroll
            for (int nt = 0; nt < 4; nt++) {
                const uint32_t bk = kst + (wn + nt * 8 + g) * 256;
                uint32_t bf[2];
                bf[0] = lds32(bk + (c0 ^ xr));
                bf[1] = lds32(bk + (c1 ^ xr));
                mma_tf32_16n8k8(sacc[0][nt], a[0], bf);
                mma_tf32_16n8k8(sacc[1][nt], a[1], bf);
            }
        }

        #pragma unroll
        for (int mt = 0; mt < 2; mt++) {
            #pragma unroll
            for (int nt = 0; nt < 4; nt++) {
                float p0 = tf32r(__expf(sacc[mt][nt][0]));
                float p1 = tf32r(__expf(sacc[mt][nt][1]));
                float p2 = tf32r(__expf(sacc[mt][nt][2]));
                float p3 = tf32r(__expf(sacc[mt][nt][3]));
                lacc[2*mt]     += p0 + p1;
                lacc[2*mt + 1] += p2 + p3;
                const uint32_t col = (uint32_t)(wn + nt * 8 + 2 * tg);
                const uint32_t a0 = sb + SP2 + (wm + mt * 16 + g) * 256
                                    + ((col * 4) ^ ((uint32_t)g << 4));
                sts64(a0, p0, p1);
                sts64(a0 + 2048, p2, p3);
            }
        }
        __syncthreads();
        CP_WAIT(0);

        #pragma unroll
        for (int kk = 0; kk < 8; kk++) {
            const uint32_t c0 = (kk * 8 + tg) * 4;
            const uint32_t c1 = c0 + 16;
            const uint32_t xr = (uint32_t)(g << 4);
            uint32_t ap[2][4];
            #pragma unroll
            for (int mt = 0; mt < 2; mt++) {
                const uint32_t pb = sb + SP2 + (wm + mt * 16 + g) * 256;
                ap[mt][0] = lds32(pb + (c0 ^ xr));
                ap[mt][1] = lds32(pb + 2048 + (c0 ^ xr));
                ap[mt][2] = lds32(pb + (c1 ^ xr));
                ap[mt][3] = lds32(pb + 2048 + (c1 ^ xr));
            }
            const uint32_t r0 = (kk * 8 + tg) * 256;
            const uint32_t r1 = r0 + 4 * 256;
            const uint32_t xv = (uint32_t)(tg << 5);
            #pragma unroll
            for (int nt = 0; nt < 4; nt++) {
                const uint32_t cb = (uint32_t)((wn + nt * 8 + g) * 4);
                uint32_t bv[2];
                bv[0] = lds32(sb + SV + r0 + (cb ^ xv));
                bv[1] = lds32(sb + SV + r1 + (cb ^ xv));
                mma_tf32_16n8k8(oacc[0][nt], ap[0], bv);
                mma_tf32_16n8k8(oacc[1][nt], ap[1], bv);
            }
        }
        __syncthreads();

        if (j + 1 < NCHUNKS) {
            const int kv = (j + 1) * 64;
            #pragma unroll
            for (int r = 0; r < 4; r++) {
                int f = t + r * 256, row = f >> 4, c = f & 15;
                uint32_t dv = row * 256 + ((c * 16) ^ ((row & 3) << 5));
                CP_ASYNC16(sb + SV + dv, Vp + (size_t)(kv + row) * 64 + c * 4);
            }
            if (j + 2 < NCHUNKS) {
                const int kk2 = (j + 2) * 64;
                #pragma unroll
                for (int r = 0; r < 4; r++) {
                    int f = t + r * 256, row = f >> 4, c = f & 15;
                    uint32_t dk = row * 256 + ((c * 16) ^ ((row & 7) << 4));
                    CP_ASYNC16(kst + dk, Kp + (size_t)(kk2 + row) * 64 + c * 4);
                }
            }
        }
        CP_COMMIT();
    }

    #pragma unroll
    for (int j = 0; j < 4; j++) {
        lacc[j] += __shfl_xor_sync(0xffffffff, lacc[j], 1);
        lacc[j] += __shfl_xor_sync(0xffffffff, lacc[j], 2);
    }
    if (tg == 0) {
        float* lp = (float*)(sm + SL2);
        #pragma unroll
        for (int j = 0; j < 4; j++) {
            int row = wm + (j >> 1) * 16 + (j & 1) * 8 + g;
            lp[(wid & 1) * 128 + row] = lacc[j];
        }
    }
    __syncthreads();

    const int b = bh / Hc, h = bh % Hc;
    float* ctxb = g_ctx + ((size_t)b * Sc + q0) * Dc + h * DHc;
    const float* lp = (const float*)(sm + SL2);
    #pragma unroll
    for (int mt = 0; mt < 2; mt++) {
        #pragma unroll
        for (int e = 0; e < 2; e++) {
            const int row = wm + mt * 16 + e * 8 + g;
            const float inv = 1.0f / (lp[row] + lp[128 + row]);
            #pragma unroll
            for (int nt = 0; nt < 4; nt++) {
                const int col = wn + nt * 8 + 2 * tg;
                float v0 = tf32r(oacc[mt][nt][2*e]     * inv);
                float v1 = tf32r(oacc[mt][nt][2*e + 1] * inv);
                *(float2*)&ctxb[(size_t)row * Dc + col] = make_float2(v0, v1);
            }
        }
    }
}

// ---------------------------------------------------------------------------
extern "C" void kernel_launch(void* const* d_in, const int* in_sizes, int n_in,
                              void* d_out, int out_size)
{
    const float* X  = (const float*)d_in[0];
    const float* Wq = (const float*)d_in[1];
    const float* bq = (const float*)d_in[2];
    const float* Wk = (const float*)d_in[3];
    const float* bk = (const float*)d_in[4];
    const float* Wv = (const float*)d_in[5];
    const float* bv = (const float*)d_in[6];
    const float* Wo = (const float*)d_in[7];
    const float* bo = (const float*)d_in[8];
    float* out = (float*)d_out;

    cudaFuncSetAttribute(gemm_mma<0>, cudaFuncAttributeMaxDynamicSharedMemorySize, SMEM_DYN);
    cudaFuncSetAttribute(gemm_mma<1>, cudaFuncAttributeMaxDynamicSharedMemorySize, SMEM_DYN);
    cudaFuncSetAttribute(attn_mma, cudaFuncAttributeMaxDynamicSharedMemorySize, ATT_SMEM);

    // Side stream: prep_x (X rounding, hides behind prep_w3) then Wo transpose,
    // then the mean/broadcast branch after QKV. Host objects only.
    cudaStream_t s2;
    cudaStreamCreateWithFlags(&s2, cudaStreamNonBlocking);
    cudaEvent_t eFork0, ePx, eWo, eQKV, eJoin;
    cudaEventCreateWithFlags(&eFork0, cudaEventDisableTiming);
    cudaEventCreateWithFlags(&ePx,    cudaEventDisableTiming);
    cudaEventCreateWithFlags(&eWo,    cudaEventDisableTiming);
    cudaEventCreateWithFlags(&eQKV,   cudaEventDisableTiming);
    cudaEventCreateWithFlags(&eJoin,  cudaEventDisableTiming);

    cudaEventRecord(eFork0, 0);
    cudaStreamWaitEvent(s2, eFork0, 0);
    prep_x<<<2048, 256, 0, s2>>>(X);
    cudaEventRecord(ePx, s2);
    prep_w1<<<dim3(24, 24), 256, 0, s2>>>(Wo);
    cudaEventRecord(eWo, s2);

    prep_w3<<<dim3(24, 24, 3), 256>>>(Wq, Wk, Wv);

    // QKV GEMM needs g_Xr (s2) + Wt[0..2] (main).
    cudaStreamWaitEvent(0, ePx, 0);
    gemm_mma<0><<<dim3(Dc/BN, Mrows/BM, 3), 256, SMEM_DYN>>>(bq, bk, bv, nullptr);

    // Branch B on s2 (needs V from gemm0 and Wt[3] from prep_w1, both s2-visible).
    cudaEventRecord(eQKV, 0);
    cudaStreamWaitEvent(s2, eQKV, 0);
    meanv_mean<<<96, 256, 0, s2>>>();
    meanrow_gemm<<<768, 256, 0, s2>>>(bo);
    bcast_out<<<3072, 256, 0, s2>>>(out);
    cudaEventRecord(eJoin, s2);

    attn_mma<<<dim3(4, 96), 256, ATT_SMEM>>>();

    // out-GEMM needs Wt[3] (from s2's prep_w1) — edge satisfied long ago.
    cudaStreamWaitEvent(0, eWo, 0);
    gemm_mma<1><<<dim3(Dc/BN, 32), 256, SMEM_DYN>>>(bo, bo, bo, out);

    cudaStreamWaitEvent(0, eJoin, 0);

    cudaEventDestroy(eFork0);
    cudaEventDestroy(ePx);
    cudaEventDestroy(eWo);
    cudaEventDestroy(eQKV);
    cudaEventDestroy(eJoin);
    cudaStreamDestroy(s2);
}

// round 15
// speedup vs baseline: 1.1321x; 1.0515x over previous
#include <cuda_runtime.h>
#include <cuda_bf16.h>
#include <cstdint>

// Problem constants
#define Bc   8
#define Sc   1024
#define Dc   768
#define Hc   12
#define DHc  64
#define Mrows (Bc*Sc)          // 8192
#define QHALF (Sc/2)           // 512

// ---------------------------------------------------------------------------
// Device scratch (allocation-free)
// ---------------------------------------------------------------------------
__device__ float g_Q[(size_t)Bc*Hc*Sc*DHc];   // tf32, pre-scaled 1/8 (q<512 valid)
__device__ float g_K[(size_t)Bc*Hc*Sc*DHc];   // tf32
__device__ float g_V[(size_t)Bc*Hc*Sc*DHc];   // tf32
__device__ float g_ctx[(size_t)Bc*Sc*Dc];     // q<512 rows used
__device__ float g_Wt[4][(size_t)Dc*Dc];      // W^T tf32-rounded: q,k,v,o
__device__ float g_Xr[(size_t)Mrows*Dc];      // X tf32-rounded
__device__ float g_mean[Bc*Dc];               // meanctx [B,D]
__device__ float g_meanrow[Bc*Dc];            // meanctx @ Wo + bo [B,D]

// ---------------------------------------------------------------------------
// Helpers
// ---------------------------------------------------------------------------
__device__ __forceinline__ uint32_t smem_u32(const void* p) {
    uint32_t a;
    asm("{ .reg .u64 t; cvta.to.shared.u64 t, %1; cvt.u32.u64 %0, t; }"
        : "=r"(a) : "l"(p));
    return a;
}
__device__ __forceinline__ float tf32r(float x) {
    float r; asm("cvt.rna.tf32.f32 %0, %1;" : "=f"(r) : "f"(x)); return r;
}
__device__ __forceinline__ uint32_t lds32(uint32_t a) {
    uint32_t v; asm volatile("ld.shared.b32 %0, [%1];" : "=r"(v) : "r"(a)); return v;
}
__device__ __forceinline__ void sts64(uint32_t a, float x, float y) {
    asm volatile("st.shared.v2.f32 [%0], {%1,%2};" :: "r"(a), "f"(x), "f"(y) : "memory");
}
#define CP_ASYNC16(dst, src) \
    asm volatile("cp.async.cg.shared.global [%0], [%1], 16;" :: "r"(dst), "l"(src) : "memory")
#define CP_COMMIT() asm volatile("cp.async.commit_group;" ::: "memory")
#define CP_WAIT(n)  asm volatile("cp.async.wait_group %0;" :: "n"(n) : "memory")

__device__ __forceinline__ void mma_tf32_16n8k8(float* d, const uint32_t* a, const uint32_t* b) {
    asm volatile(
        "mma.sync.aligned.m16n8k8.row.col.f32.tf32.tf32.f32 "
        "{%0,%1,%2,%3}, {%4,%5,%6,%7}, {%8,%9}, {%0,%1,%2,%3};"
        : "+f"(d[0]), "+f"(d[1]), "+f"(d[2]), "+f"(d[3])
        : "r"(a[0]), "r"(a[1]), "r"(a[2]), "r"(a[3]), "r"(b[0]), "r"(b[1]));
}

// ---------------------------------------------------------------------------
// prep_w3: Wt[z][n*768+k] = tf32(W[k*768+n]) for z in {0,1,2}. grid (24,24,3)
// prep_w1: same for Wo only (side stream).
// prep_x : g_Xr = tf32(X) (side stream, hides behind prep_w3).
// ---------------------------------------------------------------------------
__global__ __launch_bounds__(256)
void prep_w3(const float* __restrict__ Wq, const float* __restrict__ Wk,
             const float* __restrict__ Wv)
{
    const float* W = (blockIdx.z == 0) ? Wq : (blockIdx.z == 1) ? Wk : Wv;
    float* Wt = g_Wt[blockIdx.z];
    __shared__ float tile[32][33];
    int tx = threadIdx.x & 31, ty = threadIdx.x >> 5;
    int c0 = blockIdx.x * 32, r0 = blockIdx.y * 32;
    #pragma unroll
    for (int i = 0; i < 4; i++)
        tile[ty + 8*i][tx] = W[(size_t)(r0 + ty + 8*i) * Dc + c0 + tx];
    __syncthreads();
    #pragma unroll
    for (int i = 0; i < 4; i++)
        Wt[(size_t)(c0 + ty + 8*i) * Dc + r0 + tx] = tf32r(tile[tx][ty + 8*i]);
}

__global__ __launch_bounds__(256)
void prep_w1(const float* __restrict__ W)
{
    float* Wt = g_Wt[3];
    __shared__ float tile[32][33];
    int tx = threadIdx.x & 31, ty = threadIdx.x >> 5;
    int c0 = blockIdx.x * 32, r0 = blockIdx.y * 32;
    #pragma unroll
    for (int i = 0; i < 4; i++)
        tile[ty + 8*i][tx] = W[(size_t)(r0 + ty + 8*i) * Dc + c0 + tx];
    __syncthreads();
    #pragma unroll
    for (int i = 0; i < 4; i++)
        Wt[(size_t)(c0 + ty + 8*i) * Dc + r0 + tx] = tf32r(tile[tx][ty + 8*i]);
}

__global__ __launch_bounds__(256)
void prep_x(const float* __restrict__ X)
{
    const int N4 = Mrows * Dc / 4;
    for (int i = blockIdx.x * blockDim.x + threadIdx.x; i < N4; i += gridDim.x * blockDim.x) {
        float4 v = ((const float4*)X)[i];
        v.x = tf32r(v.x); v.y = tf32r(v.y); v.z = tf32r(v.z); v.w = tf32r(v.w);
        ((float4*)g_Xr)[i] = v;
    }
}

// ---------------------------------------------------------------------------
// mma.sync tf32 GEMM: 128x128 tile, BK=32, **128 threads (4 warps, 2Mx2N,
// warp tile 64x64)**. Per k8-step: 32 LDS -> 32 MMAs (ratio 1.0, deep ILP).
// 2 CTAs/SM (64KB smem each); 256 regs/thread available -> no spills.
// Accumulation order per output element identical to the 8-warp version.
// MODE 0: A = g_Xr, z->Q/K/V; z==0 skips tiles with in-batch row >= 512.
// MODE 1: A = g_ctx, Wt=g_Wt[3], out = d_out rows q<512.
// ---------------------------------------------------------------------------
#define BM 128
#define BN 128
#define BK 32
#define KCHUNKS (Dc/BK)           // 24
#define STAGE_BYTES 32768
#define SMEM_DYN (2*STAGE_BYTES)  // 64KB

template<int MODE>
__global__ __launch_bounds__(128, 2)
void gemm_mma(const float* __restrict__ bias0, const float* __restrict__ bias1,
              const float* __restrict__ bias2, float* __restrict__ outp)
{
    const int z  = (MODE == 0) ? (int)blockIdx.z : 3;
    const int m0 = (MODE == 0) ? (int)blockIdx.y * BM
                               : ((int)blockIdx.y >> 2) * Sc + ((int)blockIdx.y & 3) * BM;
    if (MODE == 0 && z == 0 && (m0 & (Sc - 1)) >= QHALF) return;

    extern __shared__ char smem[];
    const uint32_t smem_base = smem_u32(smem);
    const int t    = threadIdx.x;                 // 0..127
    const int wid  = t >> 5, lane = t & 31;
    const int g    = lane >> 2, tg = lane & 3;
    const int wm   = (wid & 1) * 64;              // 0 or 64
    const int wn   = (wid >> 1) * 64;             // 0 or 64

    const int n0 = blockIdx.x * BN;
    const float* __restrict__ A  = (MODE == 0) ? g_Xr : g_ctx;
    const float* __restrict__ Wt = g_Wt[z];
    const float* __restrict__ bias =
        (MODE == 0) ? (z == 0 ? bias0 : (z == 1 ? bias1 : bias2)) : bias0;

    // Loads: 8 iterations per matrix (128 rows x 8 16B-chunks / 128 threads)
    uint32_t dstoff[8];
    const float* srcA[8];
    const float* srcB[8];
    #pragma unroll
    for (int r = 0; r < 8; r++) {
        int f = t + r * 128;
        int row = f >> 3, c4 = f & 7;
        dstoff[r] = row * 128 + ((c4 * 16) ^ ((row & 7) << 4));
        srcA[r] = &A [(size_t)(m0 + row) * Dc + c4 * 4];
        srcB[r] = &Wt[(size_t)(n0 + row) * Dc + c4 * 4];
    }

    float acc[4][8][4];
    #pragma unroll
    for (int mt = 0; mt < 4; mt++)
        #pragma unroll
        for (int nt = 0; nt < 8; nt++)
            #pragma unroll
            for (int e = 0; e < 4; e++) acc[mt][nt][e] = 0.f;

    {
        uint32_t sA = smem_base, sB = smem_base + 16384;
        #pragma unroll
        for (int r = 0; r < 8; r++) {
            CP_ASYNC16(sA + dstoff[r], srcA[r]);
            CP_ASYNC16(sB + dstoff[r], srcB[r]);
        }
        CP_COMMIT();
    }

    for (int i = 0; i < KCHUNKS; i++) {
        const int s = i & 1;
        if (i + 1 < KCHUNKS) {
            uint32_t sA = smem_base + (s ^ 1) * STAGE_BYTES, sB = sA + 16384;
            const int k0 = (i + 1) * BK;
            #pragma unroll
            for (int r = 0; r < 8; r++) {
                CP_ASYNC16(sA + dstoff[r], srcA[r] + k0);
                CP_ASYNC16(sB + dstoff[r], srcB[r] + k0);
            }
            CP_COMMIT();
            CP_WAIT(1);
        } else {
            CP_WAIT(0);
        }
        __syncthreads();

        const uint32_t sA = smem_base + s * STAGE_BYTES;
        const uint32_t sB = sA + 16384;
        const uint32_t gx = (uint32_t)(g << 4);

        #pragma unroll
        for (int kk = 0; kk < 4; kk++) {
            const uint32_t c0 = (uint32_t)((kk * 8 + tg) * 4) ^ gx;
            const uint32_t c1 = (uint32_t)((kk * 8 + tg + 4) * 4) ^ gx;
            uint32_t a[4][4];
            #pragma unroll
            for (int mt = 0; mt < 4; mt++) {
                uint32_t base = sA + (wm + mt * 16 + g) * 128;
                a[mt][0] = lds32(base + c0);
                a[mt][1] = lds32(base + 1024 + c0);
                a[mt][2] = lds32(base + c1);
                a[mt][3] = lds32(base + 1024 + c1);
            }
            uint32_t b[8][2];
            #pragma unroll
            for (int nt = 0; nt < 8; nt++) {
                uint32_t base = sB + (wn + nt * 8 + g) * 128;
                b[nt][0] = lds32(base + c0);
                b[nt][1] = lds32(base + c1);
            }
            #pragma unroll
            for (int mt = 0; mt < 4; mt++)
                #pragma unroll
                for (int nt = 0; nt < 8; nt++)
                    mma_tf32_16n8k8(acc[mt][nt], a[mt], b[nt]);
        }
        __syncthreads();
    }

    #pragma unroll
    for (int nt = 0; nt < 8; nt++) {
        const int col = n0 + wn + nt * 8 + tg * 2;
        const float b0 = bias[col], b1 = bias[col + 1];
        #pragma unroll
        for (int mt = 0; mt < 4; mt++) {
            const int row = m0 + wm + mt * 16 + g;
            float x0 = acc[mt][nt][0] + b0, y0 = acc[mt][nt][1] + b1;
            float x1 = acc[mt][nt][2] + b0, y1 = acc[mt][nt][3] + b1;
            if (MODE == 0) {
                const int h = col >> 6, dh = col & 63;
                int bA = row >> 10, sL = row & 1023;
                size_t i0 = (((size_t)bA * Hc + h) * Sc + sL) * DHc + dh;
                int row1 = row + 8;
                int bB = row1 >> 10, sM = row1 & 1023;
                size_t i1 = (((size_t)bB * Hc + h) * Sc + sM) * DHc + dh;
                float* out = (z == 0) ? g_Q : (z == 1) ? g_K : g_V;
                if (z == 0) { x0 *= 0.125f; y0 *= 0.125f; x1 *= 0.125f; y1 *= 0.125f; }
                *(float2*)&out[i0] = make_float2(tf32r(x0), tf32r(y0));
                *(float2*)&out[i1] = make_float2(tf32r(x1), tf32r(y1));
            } else {
                *(float2*)&outp[(size_t)row * Dc + col] = make_float2(x0, y0);
                *(float2*)&outp[(size_t)(row + 8) * Dc + col] = make_float2(x1, y1);
            }
        }
    }
}

// ---------------------------------------------------------------------------
// meanv_mean: per-(b,h) mean of V -> g_mean. grid 96 x 256.
// ---------------------------------------------------------------------------
__global__ __launch_bounds__(256)
void meanv_mean()
{
    const int bh = blockIdx.x;
    const float* Vbh = g_V + (size_t)bh * Sc * DHc;
    __shared__ float part[4][64];
    const int t  = threadIdx.x;
    const int dh = t & 63, c = t >> 6;
    float sum = 0.f;
    for (int s = c * 256; s < (c + 1) * 256; s++) sum += Vbh[s * DHc + dh];
    part[c][dh] = sum;
    __syncthreads();
    if (t < 64)
        g_mean[bh * 64 + t] =
            tf32r((part[0][t] + part[1][t] + part[2][t] + part[3][t]) * (1.0f / Sc));
}

// meanrow_gemm: g_meanrow[b][n] = g_mean[b].Wt3[n] + bo[n]. grid 768 x 256.
__global__ __launch_bounds__(256)
void meanrow_gemm(const float* __restrict__ bo)
{
    const int idx  = blockIdx.x * 8 + (threadIdx.x >> 5);
    const int lane = threadIdx.x & 31;
    const int b = idx / Dc, n = idx % Dc;
    const float* m = g_mean + b * Dc;
    const float* w = g_Wt[3] + (size_t)n * Dc;
    float s = 0.f;
    #pragma unroll 4
    for (int d = lane; d < Dc; d += 32) s += m[d] * w[d];
    #pragma unroll
    for (int o = 16; o; o >>= 1) s += __shfl_xor_sync(0xffffffffu, s, o);
    if (lane == 0) g_meanrow[idx] = s + bo[n];
}

// bcast_out: d_out rows q in [512,1024) = g_meanrow[b]. grid 3072 x 256.
__global__ __launch_bounds__(256)
void bcast_out(float* __restrict__ out)
{
    const int i = blockIdx.x * 256 + threadIdx.x;
    const int b = i / 98304;
    const int rem = i - b * 98304;
    const int q = rem / 192;
    const int d4 = rem - q * 192;
    float4 v = ((const float4*)(g_meanrow + b * Dc))[d4];
    ((float4*)(out + ((size_t)b * Sc + QHALF + q) * Dc))[d4] = v;
}

// ---------------------------------------------------------------------------
// Flash mma attention, q<512 (R9/R14 version, verbatim). grid (4, 96), 256 thr.
// 8 warps = 4M x 2N. Smem 112KB -> 2 CTAs/SM.
// ---------------------------------------------------------------------------
#define NCHUNKS 16
#define SK0 32768
#define SK1 49152
#define SV  65536
#define SP2 81920
#define SL2 32768
#define ATT_SMEM 114688

__global__ __launch_bounds__(256, 2)
void attn_mma()
{
    extern __shared__ char sm[];
    const uint32_t sb = smem_u32(sm);
    const int t = threadIdx.x;
    const int wid = t >> 5, lane = t & 31;
    const int g = lane >> 2, tg = lane & 3;
    const int wm = (wid >> 1) * 32;
    const int wn = (wid & 1) * 32;
    const int bh = blockIdx.y;
    const int q0 = blockIdx.x * 128;
    const size_t kvbase = (size_t)bh * Sc * DHc;

    const float* Qp = g_Q + kvbase + (size_t)q0 * DHc;
    const float* Kp = g_K + kvbase;
    const float* Vp = g_V + kvbase;

    #pragma unroll
    for (int r = 0; r < 8; r++) {
        int f = t + r * 256, row = f >> 4, c = f & 15;
        CP_ASYNC16(sb + row * 256 + ((c * 16) ^ ((row & 7) << 4)),
                   Qp + (size_t)row * 64 + c * 4);
    }
    #pragma unroll
    for (int r = 0; r < 4; r++) {
        int f = t + r * 256, row = f >> 4, c = f & 15;
        uint32_t dk = row * 256 + ((c * 16) ^ ((row & 7) << 4));
        uint32_t dv = row * 256 + ((c * 16) ^ ((row & 3) << 5));
        CP_ASYNC16(sb + SK0 + dk, Kp + (size_t)row * 64 + c * 4);
        CP_ASYNC16(sb + SV  + dv, Vp + (size_t)row * 64 + c * 4);
        CP_ASYNC16(sb + SK1 + dk, Kp + (size_t)(64 + row) * 64 + c * 4);
    }
    CP_COMMIT();
    CP_WAIT(0);
    __syncthreads();

    float oacc[2][4][4];
    #pragma unroll
    for (int mt = 0; mt < 2; mt++)
        #pragma unroll
        for (int nt = 0; nt < 4; nt++)
            #pragma unroll
            for (int e = 0; e < 4; e++) oacc[mt][nt][e] = 0.f;
    float lacc[4] = {0.f, 0.f, 0.f, 0.f};

    for (int j = 0; j < NCHUNKS; j++) {
        const uint32_t kst = sb + ((j & 1) ? SK1 : SK0);

        float sacc[2][4][4];
        #pragma unroll
        for (int mt = 0; mt < 2; mt++)
            #pragma unroll
            for (int nt = 0; nt < 4; nt++)
                #pragma unroll
                for (int e = 0; e < 4; e++) sacc[mt][nt][e] = 0.f;

        #pragma unroll
        for (int kk = 0; kk < 8; kk++) {
            const uint32_t c0 = (kk * 8 + tg) * 4;
            const uint32_t c1 = c0 + 16;
            const uint32_t xr = (uint32_t)(g << 4);
            uint32_t a[2][4];
            #pragma unroll
            for (int mt = 0; mt < 2; mt++) {
                const uint32_t b0a = sb + (wm + mt * 16 + g) * 256;
                a[mt][0] = lds32(b0a + (c0 ^ xr));
                a[mt][1] = lds32(b0a + 2048 + (c0 ^ xr));
                a[mt][2] = lds32(b0a + (c1 ^ xr));
                a[mt][3] = lds32(b0a + 2048 + (c1 ^ xr));
            }
            #pragma unroll
            for (int nt = 0; nt < 4; nt++) {
                const uint32_t bk = kst + (wn + nt * 8 + g) * 256;
                uint32_t bf[2];
                bf[0] = lds32(bk + (c0 ^ xr));
                bf[1] = lds32(bk + (c1 ^ xr));
                mma_tf32_16n8k8(sacc[0][nt], a[0], bf);
                mma_tf32_16n8k8(sacc[1][nt], a[1], bf);
            }
        }

        #pragma unroll
        for (int mt = 0; mt < 2; mt++) {
            #pragma unroll
            for (int nt = 0; nt < 4; nt++) {
                float p0 = tf32r(__expf(sacc[mt][nt][0]));
                float p1 = tf32r(__expf(sacc[mt][nt][1]));
                float p2 = tf32r(__expf(sacc[mt][nt][2]));
                float p3 = tf32r(__expf(sacc[mt][nt][3]));
                lacc[2*mt]     += p0 + p1;
                lacc[2*mt + 1] += p2 + p3;
                const uint32_t col = (uint32_t)(wn + nt * 8 + 2 * tg);
                const uint32_t a0 = sb + SP2 + (wm + mt * 16 + g) * 256
                                    + ((col * 4) ^ ((uint32_t)g << 4));
                sts64(a0, p0, p1);
                sts64(a0 + 2048, p2, p3);
            }
        }
        __syncthreads();
        CP_WAIT(0);

        #pragma unroll
        for (int kk = 0; kk < 8; kk++) {
            const uint32_t c0 = (kk * 8 + tg) * 4;
            const uint32_t c1 = c0 + 16;
            const uint32_t xr = (uint32_t)(g << 4);
            uint32_t ap[2][4];
            #pragma unroll
            for (int mt = 0; mt < 2; mt++) {
                const uint32_t pb = sb + SP2 + (wm + mt * 16 + g) * 256;
                ap[mt][0] = lds32(pb + (c0 ^ xr));
                ap[mt][1] = lds32(pb + 2048 + (c0 ^ xr));
                ap[mt][2] = lds32(pb + (c1 ^ xr));
                ap[mt][3] = lds32(pb + 2048 + (c1 ^ xr));
            }
            const uint32_t r0 = (kk * 8 + tg) * 256;
            const uint32_t r1 = r0 + 4 * 256;
            const uint32_t xv = (uint32_t)(tg << 5);
            #pragma unroll
            for (int nt = 0; nt < 4; nt++) {
                const uint32_t cb = (uint32_t)((wn + nt * 8 + g) * 4);
                uint32_t bv[2];
                bv[0] = lds32(sb + SV + r0 + (cb ^ xv));
                bv[1] = lds32(sb + SV + r1 + (cb ^ xv));
                mma_tf32_16n8k8(oacc[0][nt], ap[0], bv);
                mma_tf32_16n8k8(oacc[1][nt], ap[1], bv);
            }
        }
        __syncthreads();

        if (j + 1 < NCHUNKS) {
            const int kv = (j + 1) * 64;
            #pragma unroll
            for (int r = 0; r < 4; r++) {
                int f = t + r * 256, row = f >> 4, c = f & 15;
                uint32_t dv = row * 256 + ((c * 16) ^ ((row & 3) << 5));
                CP_ASYNC16(sb + SV + dv, Vp + (size_t)(kv + row) * 64 + c * 4);
            }
            if (j + 2 < NCHUNKS) {
                const int kk2 = (j + 2) * 64;
                #pragma unroll
                for (int r = 0; r < 4; r++) {
                    int f = t + r * 256, row = f >> 4, c = f & 15;
                    uint32_t dk = row * 256 + ((c * 16) ^ ((row & 7) << 4));
                    CP_ASYNC16(kst + dk, Kp + (size_t)(kk2 + row) * 64 + c * 4);
                }
            }
        }
        CP_COMMIT();
    }

    #pragma unroll
    for (int j = 0; j < 4; j++) {
        lacc[j] += __shfl_xor_sync(0xffffffff, lacc[j], 1);
        lacc[j] += __shfl_xor_sync(0xffffffff, lacc[j], 2);
    }
    if (tg == 0) {
        float* lp = (float*)(sm + SL2);
        #pragma unroll
        for (int j = 0; j < 4; j++) {
            int row = wm + (j >> 1) * 16 + (j & 1) * 8 + g;
            lp[(wid & 1) * 128 + row] = lacc[j];
        }
    }
    __syncthreads();

    const int b = bh / Hc, h = bh % Hc;
    float* ctxb = g_ctx + ((size_t)b * Sc + q0) * Dc + h * DHc;
    const float* lp = (const float*)(sm + SL2);
    #pragma unroll
    for (int mt = 0; mt < 2; mt++) {
        #pragma unroll
        for (int e = 0; e < 2; e++) {
            const int row = wm + mt * 16 + e * 8 + g;
            const float inv = 1.0f / (lp[row] + lp[128 + row]);
            #pragma unroll
            for (int nt = 0; nt < 4; nt++) {
                const int col = wn + nt * 8 + 2 * tg;
                float v0 = tf32r(oacc[mt][nt][2*e]     * inv);
                float v1 = tf32r(oacc[mt][nt][2*e + 1] * inv);
                *(float2*)&ctxb[(size_t)row * Dc + col] = make_float2(v0, v1);
            }
        }
    }
}

// ---------------------------------------------------------------------------
extern "C" void kernel_launch(void* const* d_in, const int* in_sizes, int n_in,
                              void* d_out, int out_size)
{
    const float* X  = (const float*)d_in[0];
    const float* Wq = (const float*)d_in[1];
    const float* bq = (const float*)d_in[2];
    const float* Wk = (const float*)d_in[3];
    const float* bk = (const float*)d_in[4];
    const float* Wv = (const float*)d_in[5];
    const float* bv = (const float*)d_in[6];
    const float* Wo = (const float*)d_in[7];
    const float* bo = (const float*)d_in[8];
    float* out = (float*)d_out;

    cudaFuncSetAttribute(gemm_mma<0>, cudaFuncAttributeMaxDynamicSharedMemorySize, SMEM_DYN);
    cudaFuncSetAttribute(gemm_mma<1>, cudaFuncAttributeMaxDynamicSharedMemorySize, SMEM_DYN);
    cudaFuncSetAttribute(attn_mma, cudaFuncAttributeMaxDynamicSharedMemorySize, ATT_SMEM);

    // Side stream: prep_x (X rounding, hides behind prep_w3) then Wo transpose,
    // then the mean/broadcast branch after QKV. Host objects only.
    cudaStream_t s2;
    cudaStreamCreateWithFlags(&s2, cudaStreamNonBlocking);
    cudaEvent_t eFork0, ePx, eWo, eQKV, eJoin;
    cudaEventCreateWithFlags(&eFork0, cudaEventDisableTiming);
    cudaEventCreateWithFlags(&ePx,    cudaEventDisableTiming);
    cudaEventCreateWithFlags(&eWo,    cudaEventDisableTiming);
    cudaEventCreateWithFlags(&eQKV,   cudaEventDisableTiming);
    cudaEventCreateWithFlags(&eJoin,  cudaEventDisableTiming);

    cudaEventRecord(eFork0, 0);
    cudaStreamWaitEvent(s2, eFork0, 0);
    prep_x<<<2048, 256, 0, s2>>>(X);
    cudaEventRecord(ePx, s2);
    prep_w1<<<dim3(24, 24), 256, 0, s2>>>(Wo);
    cudaEventRecord(eWo, s2);

    prep_w3<<<dim3(24, 24, 3), 256>>>(Wq, Wk, Wv);

    // QKV GEMM needs g_Xr (s2) + Wt[0..2] (main).
    cudaStreamWaitEvent(0, ePx, 0);
    gemm_mma<0><<<dim3(Dc/BN, Mrows/BM, 3), 128, SMEM_DYN>>>(bq, bk, bv, nullptr);

    // Branch B on s2 (needs V from gemm0 and Wt[3] from prep_w1, both s2-visible).
    cudaEventRecord(eQKV, 0);
    cudaStreamWaitEvent(s2, eQKV, 0);
    meanv_mean<<<96, 256, 0, s2>>>();
    meanrow_gemm<<<768, 256, 0, s2>>>(bo);
    bcast_out<<<3072, 256, 0, s2>>>(out);
    cudaEventRecord(eJoin, s2);

    attn_mma<<<dim3(4, 96), 256, ATT_SMEM>>>();

    // out-GEMM needs Wt[3] (from s2's prep_w1) — edge satisfied long ago.
    cudaStreamWaitEvent(0, eWo, 0);
    gemm_mma<1><<<dim3(Dc/BN, 32), 128, SMEM_DYN>>>(bo, bo, bo, out);

    cudaStreamWaitEvent(0, eJoin, 0);

    cudaEventDestroy(eFork0);
    cudaEventDestroy(ePx);
    cudaEventDestroy(eWo);
    cudaEventDestroy(eQKV);
    cudaEventDestroy(eJoin);
    cudaStreamDestroy(s2);
}

// round 16
// speedup vs baseline: 1.1576x; 1.0225x over previous
#include <cuda_runtime.h>
#include <cuda_bf16.h>
#include <cstdint>

// Problem constants
#define Bc   8
#define Sc   1024
#define Dc   768
#define Hc   12
#define DHc  64
#define Mrows (Bc*Sc)          // 8192
#define QHALF (Sc/2)           // 512

// ---------------------------------------------------------------------------
// Device scratch (allocation-free)
// ---------------------------------------------------------------------------
__device__ float g_Q[(size_t)Bc*Hc*Sc*DHc];   // tf32, pre-scaled 1/8 (q<512 valid)
__device__ float g_K[(size_t)Bc*Hc*Sc*DHc];   // tf32
__device__ float g_V[(size_t)Bc*Hc*Sc*DHc];   // tf32
__device__ float g_ctx[(size_t)Bc*Sc*Dc];     // q<512 rows used
__device__ float g_Wt[4][(size_t)Dc*Dc];      // W^T tf32-rounded: q,k,v,o
__device__ float g_Xr[(size_t)Mrows*Dc];      // X tf32-rounded
__device__ float g_mean[Bc*Dc];               // meanctx [B,D]
__device__ float g_meanrow[Bc*Dc];            // meanctx @ Wo + bo [B,D]

// ---------------------------------------------------------------------------
// Helpers
// ---------------------------------------------------------------------------
__device__ __forceinline__ uint32_t smem_u32(const void* p) {
    uint32_t a;
    asm("{ .reg .u64 t; cvta.to.shared.u64 t, %1; cvt.u32.u64 %0, t; }"
        : "=r"(a) : "l"(p));
    return a;
}
__device__ __forceinline__ float tf32r(float x) {
    float r; asm("cvt.rna.tf32.f32 %0, %1;" : "=f"(r) : "f"(x)); return r;
}
__device__ __forceinline__ uint32_t lds32(uint32_t a) {
    uint32_t v; asm volatile("ld.shared.b32 %0, [%1];" : "=r"(v) : "r"(a)); return v;
}
__device__ __forceinline__ void sts64(uint32_t a, float x, float y) {
    asm volatile("st.shared.v2.f32 [%0], {%1,%2};" :: "r"(a), "f"(x), "f"(y) : "memory");
}
#define CP_ASYNC16(dst, src) \
    asm volatile("cp.async.cg.shared.global [%0], [%1], 16;" :: "r"(dst), "l"(src) : "memory")
#define CP_COMMIT() asm volatile("cp.async.commit_group;" ::: "memory")
#define CP_WAIT(n)  asm volatile("cp.async.wait_group %0;" :: "n"(n) : "memory")

__device__ __forceinline__ void mma_tf32_16n8k8(float* d, const uint32_t* a, const uint32_t* b) {
    asm volatile(
        "mma.sync.aligned.m16n8k8.row.col.f32.tf32.tf32.f32 "
        "{%0,%1,%2,%3}, {%4,%5,%6,%7}, {%8,%9}, {%0,%1,%2,%3};"
        : "+f"(d[0]), "+f"(d[1]), "+f"(d[2]), "+f"(d[3])
        : "r"(a[0]), "r"(a[1]), "r"(a[2]), "r"(a[3]), "r"(b[0]), "r"(b[1]));
}

// ---------------------------------------------------------------------------
// prep_w3 / prep_w1 / prep_x (unchanged from R15)
// ---------------------------------------------------------------------------
__global__ __launch_bounds__(256)
void prep_w3(const float* __restrict__ Wq, const float* __restrict__ Wk,
             const float* __restrict__ Wv)
{
    const float* W = (blockIdx.z == 0) ? Wq : (blockIdx.z == 1) ? Wk : Wv;
    float* Wt = g_Wt[blockIdx.z];
    __shared__ float tile[32][33];
    int tx = threadIdx.x & 31, ty = threadIdx.x >> 5;
    int c0 = blockIdx.x * 32, r0 = blockIdx.y * 32;
    #pragma unroll
    for (int i = 0; i < 4; i++)
        tile[ty + 8*i][tx] = W[(size_t)(r0 + ty + 8*i) * Dc + c0 + tx];
    __syncthreads();
    #pragma unroll
    for (int i = 0; i < 4; i++)
        Wt[(size_t)(c0 + ty + 8*i) * Dc + r0 + tx] = tf32r(tile[tx][ty + 8*i]);
}

__global__ __launch_bounds__(256)
void prep_w1(const float* __restrict__ W)
{
    float* Wt = g_Wt[3];
    __shared__ float tile[32][33];
    int tx = threadIdx.x & 31, ty = threadIdx.x >> 5;
    int c0 = blockIdx.x * 32, r0 = blockIdx.y * 32;
    #pragma unroll
    for (int i = 0; i < 4; i++)
        tile[ty + 8*i][tx] = W[(size_t)(r0 + ty + 8*i) * Dc + c0 + tx];
    __syncthreads();
    #pragma unroll
    for (int i = 0; i < 4; i++)
        Wt[(size_t)(c0 + ty + 8*i) * Dc + r0 + tx] = tf32r(tile[tx][ty + 8*i]);
}

__global__ __launch_bounds__(256)
void prep_x(const float* __restrict__ X)
{
    const int N4 = Mrows * Dc / 4;
    for (int i = blockIdx.x * blockDim.x + threadIdx.x; i < N4; i += gridDim.x * blockDim.x) {
        float4 v = ((const float4*)X)[i];
        v.x = tf32r(v.x); v.y = tf32r(v.y); v.z = tf32r(v.z); v.w = tf32r(v.w);
        ((float4*)g_Xr)[i] = v;
    }
}

// ---------------------------------------------------------------------------
// mma.sync tf32 GEMM (R15 version, verbatim): 128x128 tile, BK=32,
// 128 threads (4 warps, 2Mx2N, warp 64x64), 2-stage cp.async, 2 CTAs/SM.
// ---------------------------------------------------------------------------
#define BM 128
#define BN 128
#define BK 32
#define KCHUNKS (Dc/BK)           // 24
#define STAGE_BYTES 32768
#define SMEM_DYN (2*STAGE_BYTES)  // 64KB

template<int MODE>
__global__ __launch_bounds__(128, 2)
void gemm_mma(const float* __restrict__ bias0, const float* __restrict__ bias1,
              const float* __restrict__ bias2, float* __restrict__ outp)
{
    const int z  = (MODE == 0) ? (int)blockIdx.z : 3;
    const int m0 = (MODE == 0) ? (int)blockIdx.y * BM
                               : ((int)blockIdx.y >> 2) * Sc + ((int)blockIdx.y & 3) * BM;
    if (MODE == 0 && z == 0 && (m0 & (Sc - 1)) >= QHALF) return;

    extern __shared__ char smem[];
    const uint32_t smem_base = smem_u32(smem);
    const int t    = threadIdx.x;
    const int wid  = t >> 5, lane = t & 31;
    const int g    = lane >> 2, tg = lane & 3;
    const int wm   = (wid & 1) * 64;
    const int wn   = (wid >> 1) * 64;

    const int n0 = blockIdx.x * BN;
    const float* __restrict__ A  = (MODE == 0) ? g_Xr : g_ctx;
    const float* __restrict__ Wt = g_Wt[z];
    const float* __restrict__ bias =
        (MODE == 0) ? (z == 0 ? bias0 : (z == 1 ? bias1 : bias2)) : bias0;

    uint32_t dstoff[8];
    const float* srcA[8];
    const float* srcB[8];
    #pragma unroll
    for (int r = 0; r < 8; r++) {
        int f = t + r * 128;
        int row = f >> 3, c4 = f & 7;
        dstoff[r] = row * 128 + ((c4 * 16) ^ ((row & 7) << 4));
        srcA[r] = &A [(size_t)(m0 + row) * Dc + c4 * 4];
        srcB[r] = &Wt[(size_t)(n0 + row) * Dc + c4 * 4];
    }

    float acc[4][8][4];
    #pragma unroll
    for (int mt = 0; mt < 4; mt++)
        #pragma unroll
        for (int nt = 0; nt < 8; nt++)
            #pragma unroll
            for (int e = 0; e < 4; e++) acc[mt][nt][e] = 0.f;

    {
        uint32_t sA = smem_base, sB = smem_base + 16384;
        #pragma unroll
        for (int r = 0; r < 8; r++) {
            CP_ASYNC16(sA + dstoff[r], srcA[r]);
            CP_ASYNC16(sB + dstoff[r], srcB[r]);
        }
        CP_COMMIT();
    }

    for (int i = 0; i < KCHUNKS; i++) {
        const int s = i & 1;
        if (i + 1 < KCHUNKS) {
            uint32_t sA = smem_base + (s ^ 1) * STAGE_BYTES, sB = sA + 16384;
            const int k0 = (i + 1) * BK;
            #pragma unroll
            for (int r = 0; r < 8; r++) {
                CP_ASYNC16(sA + dstoff[r], srcA[r] + k0);
                CP_ASYNC16(sB + dstoff[r], srcB[r] + k0);
            }
            CP_COMMIT();
            CP_WAIT(1);
        } else {
            CP_WAIT(0);
        }
        __syncthreads();

        const uint32_t sA = smem_base + s * STAGE_BYTES;
        const uint32_t sB = sA + 16384;
        const uint32_t gx = (uint32_t)(g << 4);

        #pragma unroll
        for (int kk = 0; kk < 4; kk++) {
            const uint32_t c0 = (uint32_t)((kk * 8 + tg) * 4) ^ gx;
            const uint32_t c1 = (uint32_t)((kk * 8 + tg + 4) * 4) ^ gx;
            uint32_t a[4][4];
            #pragma unroll
            for (int mt = 0; mt < 4; mt++) {
                uint32_t base = sA + (wm + mt * 16 + g) * 128;
                a[mt][0] = lds32(base + c0);
                a[mt][1] = lds32(base + 1024 + c0);
                a[mt][2] = lds32(base + c1);
                a[mt][3] = lds32(base + 1024 + c1);
            }
            uint32_t b[8][2];
            #pragma unroll
            for (int nt = 0; nt < 8; nt++) {
                uint32_t base = sB + (wn + nt * 8 + g) * 128;
                b[nt][0] = lds32(base + c0);
                b[nt][1] = lds32(base + c1);
            }
            #pragma unroll
            for (int mt = 0; mt < 4; mt++)
                #pragma unroll
                for (int nt = 0; nt < 8; nt++)
                    mma_tf32_16n8k8(acc[mt][nt], a[mt], b[nt]);
        }
        __syncthreads();
    }

    #pragma unroll
    for (int nt = 0; nt < 8; nt++) {
        const int col = n0 + wn + nt * 8 + tg * 2;
        const float b0 = bias[col], b1 = bias[col + 1];
        #pragma unroll
        for (int mt = 0; mt < 4; mt++) {
            const int row = m0 + wm + mt * 16 + g;
            float x0 = acc[mt][nt][0] + b0, y0 = acc[mt][nt][1] + b1;
            float x1 = acc[mt][nt][2] + b0, y1 = acc[mt][nt][3] + b1;
            if (MODE == 0) {
                const int h = col >> 6, dh = col & 63;
                int bA = row >> 10, sL = row & 1023;
                size_t i0 = (((size_t)bA * Hc + h) * Sc + sL) * DHc + dh;
                int row1 = row + 8;
                int bB = row1 >> 10, sM = row1 & 1023;
                size_t i1 = (((size_t)bB * Hc + h) * Sc + sM) * DHc + dh;
                float* out = (z == 0) ? g_Q : (z == 1) ? g_K : g_V;
                if (z == 0) { x0 *= 0.125f; y0 *= 0.125f; x1 *= 0.125f; y1 *= 0.125f; }
                *(float2*)&out[i0] = make_float2(tf32r(x0), tf32r(y0));
                *(float2*)&out[i1] = make_float2(tf32r(x1), tf32r(y1));
            } else {
                *(float2*)&outp[(size_t)row * Dc + col] = make_float2(x0, y0);
                *(float2*)&outp[(size_t)(row + 8) * Dc + col] = make_float2(x1, y1);
            }
        }
    }
}

// ---------------------------------------------------------------------------
// meanv_mean / meanrow_gemm / bcast_out (unchanged)
// ---------------------------------------------------------------------------
__global__ __launch_bounds__(256)
void meanv_mean()
{
    const int bh = blockIdx.x;
    const float* Vbh = g_V + (size_t)bh * Sc * DHc;
    __shared__ float part[4][64];
    const int t  = threadIdx.x;
    const int dh = t & 63, c = t >> 6;
    float sum = 0.f;
    for (int s = c * 256; s < (c + 1) * 256; s++) sum += Vbh[s * DHc + dh];
    part[c][dh] = sum;
    __syncthreads();
    if (t < 64)
        g_mean[bh * 64 + t] =
            tf32r((part[0][t] + part[1][t] + part[2][t] + part[3][t]) * (1.0f / Sc));
}

__global__ __launch_bounds__(256)
void meanrow_gemm(const float* __restrict__ bo)
{
    const int idx  = blockIdx.x * 8 + (threadIdx.x >> 5);
    const int lane = threadIdx.x & 31;
    const int b = idx / Dc, n = idx % Dc;
    const float* m = g_mean + b * Dc;
    const float* w = g_Wt[3] + (size_t)n * Dc;
    float s = 0.f;
    #pragma unroll 4
    for (int d = lane; d < Dc; d += 32) s += m[d] * w[d];
    #pragma unroll
    for (int o = 16; o; o >>= 1) s += __shfl_xor_sync(0xffffffffu, s, o);
    if (lane == 0) g_meanrow[idx] = s + bo[n];
}

__global__ __launch_bounds__(256)
void bcast_out(float* __restrict__ out)
{
    const int i = blockIdx.x * 256 + threadIdx.x;
    const int b = i / 98304;
    const int rem = i - b * 98304;
    const int q = rem / 192;
    const int d4 = rem - q * 192;
    float4 v = ((const float4*)(g_meanrow + b * Dc))[d4];
    ((float4*)(out + ((size_t)b * Sc + QHALF + q) * Dc))[d4] = v;
}

// ---------------------------------------------------------------------------
// Flash mma attention, q<512. 128 threads (4 warps); each warp owns 32 FULL
// query rows (wm = wid*32, all 64 cols). Per kk: 24 LDS -> 16 MMAs.
// l is complete per-warp after tg-shuffles (no cross-warp reduce).
// Smem identical to R15: Q 32K | K0 16K | K1 16K | V 16K | P 32K = 112KB,
// 2 CTAs/SM. Per-chunk sync structure unchanged.
// ---------------------------------------------------------------------------
#define NCHUNKS 16
#define SK0 32768
#define SK1 49152
#define SV  65536
#define SP2 81920
#define ATT_SMEM 114688

__global__ __launch_bounds__(128, 2)
void attn_mma()
{
    extern __shared__ char sm[];
    const uint32_t sb = smem_u32(sm);
    const int t = threadIdx.x;                 // 0..127
    const int wid = t >> 5, lane = t & 31;
    const int g = lane >> 2, tg = lane & 3;
    const int wm = wid * 32;                   // 0,32,64,96 (full-width rows)
    const int bh = blockIdx.y;
    const int q0 = blockIdx.x * 128;
    const size_t kvbase = (size_t)bh * Sc * DHc;

    const float* Qp = g_Q + kvbase + (size_t)q0 * DHc;
    const float* Kp = g_K + kvbase;
    const float* Vp = g_V + kvbase;

    // Prologue: Q (128x64), K0, V0, K1  (one group); 128 threads
    #pragma unroll
    for (int r = 0; r < 16; r++) {
        int f = t + r * 128, row = f >> 4, c = f & 15;
        CP_ASYNC16(sb + row * 256 + ((c * 16) ^ ((row & 7) << 4)),
                   Qp + (size_t)row * 64 + c * 4);
    }
    #pragma unroll
    for (int r = 0; r < 8; r++) {
        int f = t + r * 128, row = f >> 4, c = f & 15;
        uint32_t dk = row * 256 + ((c * 16) ^ ((row & 7) << 4));
        uint32_t dv = row * 256 + ((c * 16) ^ ((row & 3) << 5));
        CP_ASYNC16(sb + SK0 + dk, Kp + (size_t)row * 64 + c * 4);
        CP_ASYNC16(sb + SV  + dv, Vp + (size_t)row * 64 + c * 4);
        CP_ASYNC16(sb + SK1 + dk, Kp + (size_t)(64 + row) * 64 + c * 4);
    }
    CP_COMMIT();
    CP_WAIT(0);
    __syncthreads();

    float oacc[2][8][4];
    #pragma unroll
    for (int mt = 0; mt < 2; mt++)
        #pragma unroll
        for (int nt = 0; nt < 8; nt++)
            #pragma unroll
            for (int e = 0; e < 4; e++) oacc[mt][nt][e] = 0.f;
    float lacc[4] = {0.f, 0.f, 0.f, 0.f};

    for (int j = 0; j < NCHUNKS; j++) {
        const uint32_t kst = sb + ((j & 1) ? SK1 : SK0);

        // ---- S = Q @ K_j^T  (warp: 32 rows x 64 cols) ----
        float sacc[2][8][4];
        #pragma unroll
        for (int mt = 0; mt < 2; mt++)
            #pragma unroll
            for (int nt = 0; nt < 8; nt++)
                #pragma unroll
                for (int e = 0; e < 4; e++) sacc[mt][nt][e] = 0.f;

        #pragma unroll
        for (int kk = 0; kk < 8; kk++) {
            const uint32_t c0 = (kk * 8 + tg) * 4;
            const uint32_t c1 = c0 + 16;
            const uint32_t xr = (uint32_t)(g << 4);
            uint32_t a[2][4];
            #pragma unroll
            for (int mt = 0; mt < 2; mt++) {
                const uint32_t b0a = sb + (wm + mt * 16 + g) * 256;
                a[mt][0] = lds32(b0a + (c0 ^ xr));
                a[mt][1] = lds32(b0a + 2048 + (c0 ^ xr));
                a[mt][2] = lds32(b0a + (c1 ^ xr));
                a[mt][3] = lds32(b0a + 2048 + (c1 ^ xr));
            }
            #pragma unroll
            for (int nt = 0; nt < 8; nt++) {
                const uint32_t bk = kst + (nt * 8 + g) * 256;
                uint32_t bf[2];
                bf[0] = lds32(bk + (c0 ^ xr));
                bf[1] = lds32(bk + (c1 ^ xr));
                mma_tf32_16n8k8(sacc[0][nt], a[0], bf);
                mma_tf32_16n8k8(sacc[1][nt], a[1], bf);
            }
        }

        // ---- exp, l accumulate, P -> smem (own rows, all 64 cols) ----
        #pragma unroll
        for (int mt = 0; mt < 2; mt++) {
            #pragma unroll
            for (int nt = 0; nt < 8; nt++) {
                float p0 = tf32r(__expf(sacc[mt][nt][0]));
                float p1 = tf32r(__expf(sacc[mt][nt][1]));
                float p2 = tf32r(__expf(sacc[mt][nt][2]));
                float p3 = tf32r(__expf(sacc[mt][nt][3]));
                lacc[2*mt]     += p0 + p1;
                lacc[2*mt + 1] += p2 + p3;
                const uint32_t col = (uint32_t)(nt * 8 + 2 * tg);
                const uint32_t a0 = sb + SP2 + (wm + mt * 16 + g) * 256
                                    + ((col * 4) ^ ((uint32_t)g << 4));
                sts64(a0, p0, p1);
                sts64(a0 + 2048, p2, p3);
            }
        }
        __syncthreads();        // V_j visibility (+ stage-reuse ordering)
        CP_WAIT(0);             // V_j (and K_{j+1}) arrived

        // ---- O += P @ V_j ----
        #pragma unroll
        for (int kk = 0; kk < 8; kk++) {
            const uint32_t c0 = (kk * 8 + tg) * 4;
            const uint32_t c1 = c0 + 16;
            const uint32_t xr = (uint32_t)(g << 4);
            uint32_t ap[2][4];
            #pragma unroll
            for (int mt = 0; mt < 2; mt++) {
                const uint32_t pb = sb + SP2 + (wm + mt * 16 + g) * 256;
                ap[mt][0] = lds32(pb + (c0 ^ xr));
                ap[mt][1] = lds32(pb + 2048 + (c0 ^ xr));
                ap[mt][2] = lds32(pb + (c1 ^ xr));
                ap[mt][3] = lds32(pb + 2048 + (c1 ^ xr));
            }
            const uint32_t r0 = (kk * 8 + tg) * 256;
            const uint32_t r1 = r0 + 4 * 256;
            const uint32_t xv = (uint32_t)(tg << 5);
            #pragma unroll
            for (int nt = 0; nt < 8; nt++) {
                const uint32_t cb = (uint32_t)((nt * 8 + g) * 4);
                uint32_t bv[2];
                bv[0] = lds32(sb + SV + r0 + (cb ^ xv));
                bv[1] = lds32(sb + SV + r1 + (cb ^ xv));
                mma_tf32_16n8k8(oacc[0][nt], ap[0], bv);
                mma_tf32_16n8k8(oacc[1][nt], ap[1], bv);
            }
        }
        __syncthreads();        // all warps done reading V_j, K_j

        // ---- issue V_{j+1} and K_{j+2} ----
        if (j + 1 < NCHUNKS) {
            const int kv = (j + 1) * 64;
            #pragma unroll
            for (int r = 0; r < 8; r++) {
                int f = t + r * 128, row = f >> 4, c = f & 15;
                uint32_t dv = row * 256 + ((c * 16) ^ ((row & 3) << 5));
                CP_ASYNC16(sb + SV + dv, Vp + (size_t)(kv + row) * 64 + c * 4);
            }
            if (j + 2 < NCHUNKS) {
                const int kk2 = (j + 2) * 64;
                #pragma unroll
                for (int r = 0; r < 8; r++) {
                    int f = t + r * 128, row = f >> 4, c = f & 15;
                    uint32_t dk = row * 256 + ((c * 16) ^ ((row & 7) << 4));
                    CP_ASYNC16(kst + dk, Kp + (size_t)(kk2 + row) * 64 + c * 4);
                }
            }
        }
        CP_COMMIT();
    }

    // ---- l: complete per-warp after tg-shuffles (rows are warp-private) ----
    #pragma unroll
    for (int j = 0; j < 4; j++) {
        lacc[j] += __shfl_xor_sync(0xffffffff, lacc[j], 1);
        lacc[j] += __shfl_xor_sync(0xffffffff, lacc[j], 2);
    }

    const int b = bh / Hc, h = bh % Hc;
    float* ctxb = g_ctx + ((size_t)b * Sc + q0) * Dc + h * DHc;
    #pragma unroll
    for (int mt = 0; mt < 2; mt++) {
        #pragma unroll
        for (int e = 0; e < 2; e++) {
            const int row = wm + mt * 16 + e * 8 + g;
            const float inv = 1.0f / lacc[2 * mt + e];
            #pragma unroll
            for (int nt = 0; nt < 8; nt++) {
                const int col = nt * 8 + 2 * tg;
                float v0 = tf32r(oacc[mt][nt][2*e]     * inv);
                float v1 = tf32r(oacc[mt][nt][2*e + 1] * inv);
                *(float2*)&ctxb[(size_t)row * Dc + col] = make_float2(v0, v1);
            }
        }
    }
}

// ---------------------------------------------------------------------------
extern "C" void kernel_launch(void* const* d_in, const int* in_sizes, int n_in,
                              void* d_out, int out_size)
{
    const float* X  = (const float*)d_in[0];
    const float* Wq = (const float*)d_in[1];
    const float* bq = (const float*)d_in[2];
    const float* Wk = (const float*)d_in[3];
    const float* bk = (const float*)d_in[4];
    const float* Wv = (const float*)d_in[5];
    const float* bv = (const float*)d_in[6];
    const float* Wo = (const float*)d_in[7];
    const float* bo = (const float*)d_in[8];
    float* out = (float*)d_out;

    cudaFuncSetAttribute(gemm_mma<0>, cudaFuncAttributeMaxDynamicSharedMemorySize, SMEM_DYN);
    cudaFuncSetAttribute(gemm_mma<1>, cudaFuncAttributeMaxDynamicSharedMemorySize, SMEM_DYN);
    cudaFuncSetAttribute(attn_mma, cudaFuncAttributeMaxDynamicSharedMemorySize, ATT_SMEM);

    cudaStream_t s2;
    cudaStreamCreateWithFlags(&s2, cudaStreamNonBlocking);
    cudaEvent_t eFork0, ePx, eWo, eQKV, eJoin;
    cudaEventCreateWithFlags(&eFork0, cudaEventDisableTiming);
    cudaEventCreateWithFlags(&ePx,    cudaEventDisableTiming);
    cudaEventCreateWithFlags(&eWo,    cudaEventDisableTiming);
    cudaEventCreateWithFlags(&eQKV,   cudaEventDisableTiming);
    cudaEventCreateWithFlags(&eJoin,  cudaEventDisableTiming);

    cudaEventRecord(eFork0, 0);
    cudaStreamWaitEvent(s2, eFork0, 0);
    prep_x<<<2048, 256, 0, s2>>>(X);
    cudaEventRecord(ePx, s2);
    prep_w1<<<dim3(24, 24), 256, 0, s2>>>(Wo);
    cudaEventRecord(eWo, s2);

    prep_w3<<<dim3(24, 24, 3), 256>>>(Wq, Wk, Wv);

    cudaStreamWaitEvent(0, ePx, 0);
    gemm_mma<0><<<dim3(Dc/BN, Mrows/BM, 3), 128, SMEM_DYN>>>(bq, bk, bv, nullptr);

    cudaEventRecord(eQKV, 0);
    cudaStreamWaitEvent(s2, eQKV, 0);
    meanv_mean<<<96, 256, 0, s2>>>();
    meanrow_gemm<<<768, 256, 0, s2>>>(bo);
    bcast_out<<<3072, 256, 0, s2>>>(out);
    cudaEventRecord(eJoin, s2);

    attn_mma<<<dim3(4, 96), 128, ATT_SMEM>>>();

    cudaStreamWaitEvent(0, eWo, 0);
    gemm_mma<1><<<dim3(Dc/BN, 32), 128, SMEM_DYN>>>(bo, bo, bo, out);

    cudaStreamWaitEvent(0, eJoin, 0);

    cudaEventDestroy(eFork0);
    cudaEventDestroy(ePx);
    cudaEventDestroy(eWo);
    cudaEventDestroy(eQKV);
    cudaEventDestroy(eJoin);
    cudaStreamDestroy(s2);
}